// round 14
// baseline (speedup 1.0000x reference)
#include <cuda_runtime.h>
#include <math.h>
#include <stdint.h>

#define B_  4
#define S_  2048
#define D_  1024
#define H_  16
#define HD_ 64
#define MS_ (B_*S_)   // 8192

// Scratch (static device globals — no allocation)
__device__ float g_Q[(size_t)MS_ * D_];
__device__ float g_K[(size_t)MS_ * D_];
__device__ float g_V[(size_t)MS_ * D_];
__device__ float g_VT[(size_t)B_ * H_ * HD_ * S_];   // V^T per head: [bh][hd][s]
__device__ float g_C[(size_t)MS_ * D_];
__device__ float g_WT[4][(size_t)D_ * D_];      // transposed + tf32-rounded weights

#define GEMM_SMEM  (512 * 36 * 4)                           // 73728 B
// fused: Qs 32*68 | Ks 2*128*68 | Ls 32*4 | Rs 32  = 19744 floats
#define FUSED_SMEM ((32*68 + 256*68 + 32*4 + 32) * 4)       // 78976 B

// ---------------------------------------------------------------------------
// tf32 / cp.async helpers (sm_80+ ISA — compiles for plain sm_103 target)
// ---------------------------------------------------------------------------
__device__ __forceinline__ float f2tf(float f) {
    uint32_t u;
    asm("cvt.rna.tf32.f32 %0, %1;" : "=r"(u) : "f"(f));
    return __uint_as_float(u);
}

__device__ __forceinline__ void mma_tf32(float* d, const uint32_t* a, const uint32_t* b) {
    asm volatile(
        "mma.sync.aligned.m16n8k8.row.col.f32.tf32.tf32.f32 "
        "{%0,%1,%2,%3}, {%4,%5,%6,%7}, {%8,%9}, {%0,%1,%2,%3};"
        : "+f"(d[0]), "+f"(d[1]), "+f"(d[2]), "+f"(d[3])
        : "r"(a[0]), "r"(a[1]), "r"(a[2]), "r"(a[3]),
          "r"(b[0]), "r"(b[1]));
}

__device__ __forceinline__ uint32_t s32(const void* p) {
    return (uint32_t)__cvta_generic_to_shared(p);
}
__device__ __forceinline__ void cp_async16(uint32_t saddr, const void* gaddr) {
    asm volatile("cp.async.cg.shared.global [%0], [%1], 16;"
                 :: "r"(saddr), "l"(gaddr));
}
#define CP_COMMIT() asm volatile("cp.async.commit_group;")
#define CP_WAIT1()  asm volatile("cp.async.wait_group 1;")
#define CP_WAIT0()  asm volatile("cp.async.wait_group 0;")

// 128 rows x 32 cols chunk -> smem rows of stride 36 (256 threads)
__device__ __forceinline__ void cpB_chunk36(const float* G, int ld,
                                            uint32_t sbase, int tid) {
#pragma unroll
    for (int p = 0; p < 4; p++) {
        int f4 = p * 256 + tid;
        int r = f4 >> 3, c4 = (f4 & 7) * 4;
        cp_async16(sbase + (uint32_t)(r * 36 + c4) * 4, G + (size_t)r * ld + c4);
    }
}
// 64 rows x 32 cols chunk -> smem rows of stride 36 (256 threads)
__device__ __forceinline__ void cpV_chunk36(const float* G, int ld,
                                            uint32_t sbase, int tid) {
#pragma unroll
    for (int p = 0; p < 2; p++) {
        int f4 = p * 256 + tid;
        int r = f4 >> 3, c4 = (f4 & 7) * 4;
        cp_async16(sbase + (uint32_t)(r * 36 + c4) * 4, G + (size_t)r * ld + c4);
    }
}
// 128 rows x 64 cols tile -> smem rows of stride 68 (256 threads)
__device__ __forceinline__ void cpK_tile68(const float* G, int ld,
                                           uint32_t sbase, int tid) {
#pragma unroll
    for (int p = 0; p < 8; p++) {
        int f4 = p * 256 + tid;
        int r = f4 >> 4, c4 = (f4 & 15) * 4;
        cp_async16(sbase + (uint32_t)(r * 68 + c4) * 4, G + (size_t)r * ld + c4);
    }
}

// ===========================================================================
// Weight transposes (all 4 in one launch) + tf32 pre-round
// ===========================================================================
__global__ __launch_bounds__(256) void transpose4(
    const float* __restrict__ W0, const float* __restrict__ W1,
    const float* __restrict__ W2, const float* __restrict__ W3,
    float* __restrict__ O0, float* __restrict__ O1,
    float* __restrict__ O2, float* __restrict__ O3)
{
    int z = blockIdx.z;
    const float* in = (z == 0) ? W0 : (z == 1) ? W1 : (z == 2) ? W2 : W3;
    float* out      = (z == 0) ? O0 : (z == 1) ? O1 : (z == 2) ? O2 : O3;

    __shared__ float t[32][33];
    int x = blockIdx.x * 32 + threadIdx.x;
    int y = blockIdx.y * 32 + threadIdx.y;
#pragma unroll
    for (int j = 0; j < 32; j += 8)
        t[threadIdx.y + j][threadIdx.x] = in[(size_t)(y + j) * D_ + x];
    __syncthreads();
    x = blockIdx.y * 32 + threadIdx.x;
    y = blockIdx.x * 32 + threadIdx.y;
#pragma unroll
    for (int j = 0; j < 32; j += 8)
        out[(size_t)(y + j) * D_ + x] = f2tf(t[threadIdx.x][threadIdx.y + j]);
}

// ===========================================================================
// V per-head transpose: g_VT[bh][hd][s] = g_V[(b*S+s)][h*64+hd]
// ===========================================================================
__global__ __launch_bounds__(256) void vtrans(
    const float* __restrict__ V, float* __restrict__ VT)
{
    __shared__ float t[32][33];
    int bh = blockIdx.z;
    int b = bh >> 4, h = bh & 15;
    int s0 = blockIdx.x * 32, d0 = blockIdx.y * 32;
#pragma unroll
    for (int j = 0; j < 32; j += 8)
        t[threadIdx.y + j][threadIdx.x] =
            V[((size_t)b * S_ + s0 + threadIdx.y + j) * D_ + h * HD_ + d0 + threadIdx.x];
    __syncthreads();
#pragma unroll
    for (int j = 0; j < 32; j += 8)
        VT[((size_t)bh * HD_ + d0 + threadIdx.y + j) * S_ + s0 + threadIdx.x] =
            t[threadIdx.x][threadIdx.y + j];
}

// ===========================================================================
// 128x128xK MMA mainloop, BK=32: A via register prefetch + STS (optional cvt),
// B via cp.async 2-stage. As/Bs: 256 rows x 36 (two 128-row buffers each).
// ===========================================================================
template<bool CVTA>
__device__ __forceinline__ void gemm_main(
    const float* __restrict__ A, const float* __restrict__ BT,
    int K, int lda, int ldb,
    float (*As)[36], float (*Bs)[36],
    float (&acc)[4][4][4])
{
    int tid  = threadIdx.x;
    int lane = tid & 31, warp = tid >> 5;
    int g = lane >> 2, t = lane & 3;
    int wm = warp >> 2, wn = warp & 3;

    uint32_t sB = s32(Bs);
    const uint32_t BUFB = 128 * 36 * 4;
    int NT = K / 32;

    float4 pa[4];
#pragma unroll
    for (int p = 0; p < 4; p++) {
        int f4 = p * 256 + tid;
        int r = f4 >> 3, c4 = (f4 & 7) * 4;
        pa[p] = *(const float4*)(A + (size_t)r * lda + c4);
    }
    cpB_chunk36(BT, ldb, sB, tid); CP_COMMIT();
    if (NT > 1) { cpB_chunk36(BT + 32, ldb, sB + BUFB, tid); CP_COMMIT(); }

#pragma unroll
    for (int p = 0; p < 4; p++) {
        int f4 = p * 256 + tid;
        int r = f4 >> 3, c4 = (f4 & 7) * 4;
        As[r][c4 + 0] = CVTA ? f2tf(pa[p].x) : pa[p].x;
        As[r][c4 + 1] = CVTA ? f2tf(pa[p].y) : pa[p].y;
        As[r][c4 + 2] = CVTA ? f2tf(pa[p].z) : pa[p].z;
        As[r][c4 + 3] = CVTA ? f2tf(pa[p].w) : pa[p].w;
    }
    if (NT > 1) {
#pragma unroll
        for (int p = 0; p < 4; p++) {
            int f4 = p * 256 + tid;
            int r = f4 >> 3, c4 = (f4 & 7) * 4;
            pa[p] = *(const float4*)(A + (size_t)r * lda + 32 + c4);
        }
    }
    if (NT > 1) { CP_WAIT1(); } else { CP_WAIT0(); }
    __syncthreads();

    for (int it = 0; it < NT; it++) {
        int cur = (it & 1) * 128;
        if (it + 1 < NT) {
            int nb = ((it + 1) & 1) * 128;
#pragma unroll
            for (int p = 0; p < 4; p++) {
                int f4 = p * 256 + tid;
                int r = nb + (f4 >> 3), c4 = (f4 & 7) * 4;
                As[r][c4 + 0] = CVTA ? f2tf(pa[p].x) : pa[p].x;
                As[r][c4 + 1] = CVTA ? f2tf(pa[p].y) : pa[p].y;
                As[r][c4 + 2] = CVTA ? f2tf(pa[p].z) : pa[p].z;
                As[r][c4 + 3] = CVTA ? f2tf(pa[p].w) : pa[p].w;
            }
        }
        if (it + 2 < NT) {
            int k0 = (it + 2) * 32;
#pragma unroll
            for (int p = 0; p < 4; p++) {
                int f4 = p * 256 + tid;
                int r = f4 >> 3, c4 = (f4 & 7) * 4;
                pa[p] = *(const float4*)(A + (size_t)r * lda + k0 + c4);
            }
        }

#pragma unroll
        for (int kk = 0; kk < 32; kk += 8) {
            uint32_t af[4][4], bf[4][2];
#pragma unroll
            for (int mi = 0; mi < 4; mi++) {
                int mr = cur + wm * 64 + mi * 16 + g;
                af[mi][0] = __float_as_uint(As[mr][kk + t]);
                af[mi][1] = __float_as_uint(As[mr + 8][kk + t]);
                af[mi][2] = __float_as_uint(As[mr][kk + t + 4]);
                af[mi][3] = __float_as_uint(As[mr + 8][kk + t + 4]);
            }
#pragma unroll
            for (int ni = 0; ni < 4; ni++) {
                int nr = cur + wn * 32 + ni * 8 + g;
                bf[ni][0] = __float_as_uint(Bs[nr][kk + t]);
                bf[ni][1] = __float_as_uint(Bs[nr][kk + t + 4]);
            }
#pragma unroll
            for (int mi = 0; mi < 4; mi++)
#pragma unroll
                for (int ni = 0; ni < 4; ni++)
                    mma_tf32(acc[mi][ni], af[mi], bf[ni]);
        }
        __syncthreads();

        if (it + 2 < NT) {
            cpB_chunk36(BT + (it + 2) * 32, ldb,
                        sB + (uint32_t)(it & 1) * BUFB, tid);
            CP_COMMIT();
        }
        if (it + 1 < NT) {
            if (it + 2 < NT) { CP_WAIT1(); } else { CP_WAIT0(); }
            __syncthreads();
        }
    }
}

// ===========================================================================
// Fused Q/K/V projection GEMMs (grid.z selects tensor).
// ===========================================================================
__global__ __launch_bounds__(256, 2) void qkv_gemm(
    const float* __restrict__ Aq, const float* __restrict__ Ak,
    const float* __restrict__ Av,
    const float* __restrict__ Wq, const float* __restrict__ Wk,
    const float* __restrict__ Wv,
    const float* __restrict__ bq, const float* __restrict__ bk,
    const float* __restrict__ bv,
    float* __restrict__ Cq, float* __restrict__ Ck, float* __restrict__ Cv)
{
    extern __shared__ float sdyn[];
    float (*As)[36] = (float(*)[36])sdyn;         // 256 rows
    float (*Bs)[36] = (float(*)[36])sdyn + 256;   // 256 rows

    int z = blockIdx.z;
    const float* A    = (z == 0) ? Aq : (z == 1) ? Ak : Av;
    const float* BT   = (z == 0) ? Wq : (z == 1) ? Wk : Wv;
    const float* bias = (z == 0) ? bq : (z == 1) ? bk : bv;
    float*       C    = (z == 0) ? Cq : (z == 1) ? Ck : Cv;

    int m0 = blockIdx.y * 128, n0 = blockIdx.x * 128;

    float acc[4][4][4];
#pragma unroll
    for (int i = 0; i < 4; i++)
#pragma unroll
        for (int j = 0; j < 4; j++)
#pragma unroll
            for (int r = 0; r < 4; r++) acc[i][j][r] = 0.f;

    gemm_main<true>(A + (size_t)m0 * D_, BT + (size_t)n0 * D_,
                    D_, D_, D_, As, Bs, acc);

    int lane = threadIdx.x & 31, warp = threadIdx.x >> 5;
    int g = lane >> 2, t = lane & 3;
    int wm = warp >> 2, wn = warp & 3;
#pragma unroll
    for (int mi = 0; mi < 4; mi++) {
        int row = m0 + wm * 64 + mi * 16 + g;
#pragma unroll
        for (int ni = 0; ni < 4; ni++) {
            int col = n0 + wn * 32 + ni * 8 + 2 * t;
            float2 b2 = *(const float2*)(bias + col);
            float2 o0, o1;
            o0.x = f2tf(acc[mi][ni][0] + b2.x); o0.y = f2tf(acc[mi][ni][1] + b2.y);
            o1.x = f2tf(acc[mi][ni][2] + b2.x); o1.y = f2tf(acc[mi][ni][3] + b2.y);
            *(float2*)(C + (size_t)row * D_ + col)       = o0;
            *(float2*)(C + (size_t)(row + 8) * D_ + col) = o1;
        }
    }
}

// ===========================================================================
// Output projection GEMM.
// ===========================================================================
__global__ __launch_bounds__(256, 2) void out_gemm(
    const float* __restrict__ A, const float* __restrict__ BT,
    const float* __restrict__ bias, float* __restrict__ C)
{
    extern __shared__ float sdyn[];
    float (*As)[36] = (float(*)[36])sdyn;
    float (*Bs)[36] = (float(*)[36])sdyn + 256;

    int m0 = blockIdx.y * 128, n0 = blockIdx.x * 128;

    float acc[4][4][4];
#pragma unroll
    for (int i = 0; i < 4; i++)
#pragma unroll
        for (int j = 0; j < 4; j++)
#pragma unroll
            for (int r = 0; r < 4; r++) acc[i][j][r] = 0.f;

    gemm_main<false>(A + (size_t)m0 * D_, BT + (size_t)n0 * D_,
                     D_, D_, D_, As, Bs, acc);

    int lane = threadIdx.x & 31, warp = threadIdx.x >> 5;
    int g = lane >> 2, t = lane & 3;
    int wm = warp >> 2, wn = warp & 3;
#pragma unroll
    for (int mi = 0; mi < 4; mi++) {
        int row = m0 + wm * 64 + mi * 16 + g;
#pragma unroll
        for (int ni = 0; ni < 4; ni++) {
            int col = n0 + wn * 32 + ni * 8 + 2 * t;
            float2 b2 = *(const float2*)(bias + col);
            float2 o0, o1;
            o0.x = acc[mi][ni][0] + b2.x; o0.y = acc[mi][ni][1] + b2.y;
            o1.x = acc[mi][ni][2] + b2.x; o1.y = acc[mi][ni][3] + b2.y;
            *(float2*)(C + (size_t)row * D_ + col)       = o0;
            *(float2*)(C + (size_t)(row + 8) * D_ + col) = o1;
        }
    }
}

// ===========================================================================
// FUSED attention, 32-query strips (L2-resident E): CTA = 32 q x 2048 k,
// one (b,h). Phase 1: E = exp(QK/8) -> attn, row sums -> smem rinv.
// Phase 2: E read back (L2-hot), P = E*rinv overwrite, O = rinv*(E@V).
// grid (64, 64), 256 threads, 2 CTAs/SM, 79KB smem.
// ===========================================================================
__global__ __launch_bounds__(256, 2) void attn_fused(float* __restrict__ attn)
{
    extern __shared__ float sdyn[];
    // phase 1 layout
    float (*Qs)[68] = (float(*)[68])sdyn;                 // 32 rows
    float (*Ks)[68] = (float(*)[68])sdyn + 32;            // 256 rows (2 buf)
    float (*Ls)[4]  = (float(*)[4])(sdyn + 32*68 + 256*68);    // [32][4]
    float* Rs = sdyn + 32*68 + 256*68 + 32*4;             // 32 rinv
    // phase 2 layout (low region reused; Ls/Rs live above)
    float (*As)[36] = (float(*)[36])sdyn;                 // 2 x 32 rows
    float (*Vs)[36] = (float(*)[36])sdyn + 64;            // 2 x 64 rows

    int tid  = threadIdx.x;
    int lane = tid & 31, warp = tid >> 5;
    int g = lane >> 2, t = lane & 3;
    int wm = warp >> 2, wn = warp & 3;    // 2(m) x 4(n)

    int bh = blockIdx.y;
    int b = bh >> 4, h = bh & 15;
    int q0 = blockIdx.x * 32;

    const float* Qb = g_Q + ((size_t)b * S_ + q0) * D_ + h * HD_;
    const float* Kb = g_K + (size_t)b * S_ * D_ + h * HD_;
    float* Ab = attn + (size_t)bh * S_ * S_ + (size_t)q0 * S_;

    // ==================== Phase 1: E + row sums ====================
    {
        uint32_t sK = s32(Ks);
        const uint32_t BUFK = 128 * 68 * 4;

        cpK_tile68(Kb, D_, sK, tid); CP_COMMIT();
        cpK_tile68(Kb + (size_t)128 * D_, D_, sK + BUFK, tid); CP_COMMIT();

        // load Q tile 32 x 64 (pre-rounded tf32 in g_Q)
#pragma unroll
        for (int p = 0; p < 2; p++) {
            int f4 = p * 256 + tid;
            int r = f4 >> 4, c4 = (f4 & 15) * 4;
            *(float4*)(&Qs[r][c4]) = *(const float4*)(Qb + (size_t)r * D_ + c4);
        }

        float l2[2] = {0.f, 0.f};   // rows wm*16+g, wm*16+g+8

        CP_WAIT1();
        __syncthreads();

        const float scale = 0.125f;

        for (int kt = 0; kt < 16; kt++) {
            int cur = (kt & 1) * 128;

            float acc[4][4];   // [ni][reg]
#pragma unroll
            for (int j = 0; j < 4; j++)
#pragma unroll
                for (int r = 0; r < 4; r++) acc[j][r] = 0.f;

#pragma unroll
            for (int kk = 0; kk < 64; kk += 8) {
                uint32_t af[4], bf[4][2];
                int mr = wm * 16 + g;
                af[0] = __float_as_uint(Qs[mr][kk + t]);
                af[1] = __float_as_uint(Qs[mr + 8][kk + t]);
                af[2] = __float_as_uint(Qs[mr][kk + t + 4]);
                af[3] = __float_as_uint(Qs[mr + 8][kk + t + 4]);
#pragma unroll
                for (int ni = 0; ni < 4; ni++) {
                    int nr = cur + wn * 32 + ni * 8 + g;
                    bf[ni][0] = __float_as_uint(Ks[nr][kk + t]);
                    bf[ni][1] = __float_as_uint(Ks[nr][kk + t + 4]);
                }
#pragma unroll
                for (int ni = 0; ni < 4; ni++)
                    mma_tf32(acc[ni], af, bf[ni]);
            }

            int row = wm * 16 + g;
#pragma unroll
            for (int ni = 0; ni < 4; ni++) {
                int col = kt * 128 + wn * 32 + ni * 8 + 2 * t;
#pragma unroll
                for (int r = 0; r < 4; r++)
                    acc[ni][r] = __expf(acc[ni][r] * scale);
                float2 o0, o1;
                o0.x = acc[ni][0]; o0.y = acc[ni][1];
                o1.x = acc[ni][2]; o1.y = acc[ni][3];
                *(float2*)(Ab + (size_t)row * S_ + col)       = o0;
                *(float2*)(Ab + (size_t)(row + 8) * S_ + col) = o1;
                l2[0] += acc[ni][0] + acc[ni][1];
                l2[1] += acc[ni][2] + acc[ni][3];
            }
            __syncthreads();

            if (kt + 2 < 16) {
                cpK_tile68(Kb + (size_t)(kt + 2) * 128 * D_, D_,
                           sK + (uint32_t)(kt & 1) * BUFK, tid);
                CP_COMMIT();
            }
            if (kt + 1 < 16) {
                if (kt + 2 < 16) { CP_WAIT1(); } else { CP_WAIT0(); }
                __syncthreads();
            }
        }

        // reduce sums over quad lanes t (same rows)
#pragma unroll
        for (int i = 0; i < 2; i++) {
            float l = l2[i];
            l += __shfl_xor_sync(0xffffffffu, l, 1);
            l += __shfl_xor_sync(0xffffffffu, l, 2);
            l2[i] = l;
        }
        __syncthreads();   // phase-1 smem reads done before Ls writes
        if (t == 0) {
            Ls[wm * 16 + g][wn]     = l2[0];
            Ls[wm * 16 + g + 8][wn] = l2[1];
        }
        __syncthreads();
        if (tid < 32) {
            float l = Ls[tid][0] + Ls[tid][1] + Ls[tid][2] + Ls[tid][3];
            Rs[tid] = 1.0f / l;
        }
        __syncthreads();
    }

    // ==================== Phase 2: normalize + E @ V ====================
    {
        // wm = rows (2 x 16), wn = hd cols (4 x 16)
        const float* Vb = g_VT + (size_t)bh * HD_ * S_;   // [hd][s]
        uint32_t sV = s32(Vs);
        const uint32_t BUFV = 64 * 36 * 4;
        const int NT = S_ / 32;   // 64

        float acc[2][4];   // [ni][reg], warp tile 16 rows x 16 hd
#pragma unroll
        for (int j = 0; j < 2; j++)
#pragma unroll
            for (int r = 0; r < 4; r++) acc[j][r] = 0.f;

        float4 pa;   // 32 rows x 32 cols / 4 = 256 float4 -> 1 per thread
        int ar = tid >> 3, ac4 = (tid & 7) * 4;
        pa = *(const float4*)(Ab + (size_t)ar * S_ + ac4);
        cpV_chunk36(Vb, S_, sV, tid); CP_COMMIT();
        cpV_chunk36(Vb + 32, S_, sV + BUFV, tid); CP_COMMIT();

        // transform + STS chunk 0 into As buf0 (+ final prob write p = e*rinv)
        {
            float rv = Rs[ar];
            float4 pr;
            pr.x = pa.x * rv; pr.y = pa.y * rv;
            pr.z = pa.z * rv; pr.w = pa.w * rv;
            *(float4*)(Ab + (size_t)ar * S_ + ac4) = pr;
            As[ar][ac4 + 0] = f2tf(pa.x); As[ar][ac4 + 1] = f2tf(pa.y);
            As[ar][ac4 + 2] = f2tf(pa.z); As[ar][ac4 + 3] = f2tf(pa.w);
        }
        pa = *(const float4*)(Ab + (size_t)ar * S_ + 32 + ac4);
        CP_WAIT1();
        __syncthreads();

        for (int it = 0; it < NT; it++) {
            int curA = (it & 1) * 32;
            int curV = (it & 1) * 64;
            if (it + 1 < NT) {
                int nb = ((it + 1) & 1) * 32;
                int kb = (it + 1) * 32;
                float rv = Rs[ar];
                float4 pr;
                pr.x = pa.x * rv; pr.y = pa.y * rv;
                pr.z = pa.z * rv; pr.w = pa.w * rv;
                *(float4*)(Ab + (size_t)ar * S_ + kb + ac4) = pr;
                As[nb + ar][ac4 + 0] = f2tf(pa.x);
                As[nb + ar][ac4 + 1] = f2tf(pa.y);
                As[nb + ar][ac4 + 2] = f2tf(pa.z);
                As[nb + ar][ac4 + 3] = f2tf(pa.w);
            }
            if (it + 2 < NT) {
                int k0 = (it + 2) * 32;
                pa = *(const float4*)(Ab + (size_t)ar * S_ + k0 + ac4);
            }

#pragma unroll
            for (int kk = 0; kk < 32; kk += 8) {
                uint32_t af[4], bf[2][2];
                int mr = curA + wm * 16 + g;
                af[0] = __float_as_uint(As[mr][kk + t]);
                af[1] = __float_as_uint(As[mr + 8][kk + t]);
                af[2] = __float_as_uint(As[mr][kk + t + 4]);
                af[3] = __float_as_uint(As[mr + 8][kk + t + 4]);
#pragma unroll
                for (int ni = 0; ni < 2; ni++) {
                    int nr = curV + wn * 16 + ni * 8 + g;
                    bf[ni][0] = __float_as_uint(Vs[nr][kk + t]);
                    bf[ni][1] = __float_as_uint(Vs[nr][kk + t + 4]);
                }
#pragma unroll
                for (int ni = 0; ni < 2; ni++)
                    mma_tf32(acc[ni], af, bf[ni]);
            }
            __syncthreads();

            if (it + 2 < NT) {
                cpV_chunk36(Vb + (it + 2) * 32, S_,
                            sV + (uint32_t)(it & 1) * BUFV, tid);
                CP_COMMIT();
            }
            if (it + 1 < NT) {
                if (it + 2 < NT) { CP_WAIT1(); } else { CP_WAIT0(); }
                __syncthreads();
            }
        }

        // epilogue: O = rinv_row * acc
        float* Cb = g_C + ((size_t)b * S_ + q0) * D_ + h * HD_;
        int row = wm * 16 + g;
        float rv0 = Rs[row], rv1 = Rs[row + 8];
#pragma unroll
        for (int ni = 0; ni < 2; ni++) {
            int col = wn * 16 + ni * 8 + 2 * t;
            float2 o0, o1;
            o0.x = f2tf(acc[ni][0] * rv0); o0.y = f2tf(acc[ni][1] * rv0);
            o1.x = f2tf(acc[ni][2] * rv1); o1.y = f2tf(acc[ni][3] * rv1);
            *(float2*)(Cb + (size_t)row * D_ + col)       = o0;
            *(float2*)(Cb + (size_t)(row + 8) * D_ + col) = o1;
        }
    }
}

// ---------------------------------------------------------------------------
extern "C" void kernel_launch(void* const* d_in, const int* in_sizes, int n_in,
                              void* d_out, int out_size)
{
    const float* q  = (const float*)d_in[0];
    const float* k  = (const float*)d_in[1];
    const float* v  = (const float*)d_in[2];
    const float* Wq = (const float*)d_in[3];
    const float* bq = (const float*)d_in[4];
    const float* Wk = (const float*)d_in[5];
    const float* bk = (const float*)d_in[6];
    const float* Wv = (const float*)d_in[7];
    const float* bv = (const float*)d_in[8];
    const float* Wo = (const float*)d_in[9];
    const float* bo = (const float*)d_in[10];

    float* out  = (float*)d_out;
    float* attn = out + (size_t)MS_ * D_;   // tuple order: (output, attention)

    float *pQ, *pK, *pV, *pVT, *pC, *pWT;
    cudaGetSymbolAddress((void**)&pQ, g_Q);
    cudaGetSymbolAddress((void**)&pK, g_K);
    cudaGetSymbolAddress((void**)&pV, g_V);
    cudaGetSymbolAddress((void**)&pVT, g_VT);
    cudaGetSymbolAddress((void**)&pC, g_C);
    cudaGetSymbolAddress((void**)&pWT, g_WT);

    cudaFuncSetAttribute(qkv_gemm,
                         cudaFuncAttributeMaxDynamicSharedMemorySize, GEMM_SMEM);
    cudaFuncSetAttribute(out_gemm,
                         cudaFuncAttributeMaxDynamicSharedMemorySize, GEMM_SMEM);
    cudaFuncSetAttribute(attn_fused,
                         cudaFuncAttributeMaxDynamicSharedMemorySize, FUSED_SMEM);

    float* WTq = pWT + 0 * (size_t)D_ * D_;
    float* WTk = pWT + 1 * (size_t)D_ * D_;
    float* WTv = pWT + 2 * (size_t)D_ * D_;
    float* WTo = pWT + 3 * (size_t)D_ * D_;

    transpose4<<<dim3(32, 32, 4), dim3(32, 8)>>>(Wq, Wk, Wv, Wo,
                                                 WTq, WTk, WTv, WTo);

    qkv_gemm<<<dim3(8, 64, 3), 256, GEMM_SMEM>>>(q, k, v, WTq, WTk, WTv,
                                                 bq, bk, bv, pQ, pK, pV);

    vtrans<<<dim3(64, 2, 64), dim3(32, 8)>>>(pV, pVT);

    attn_fused<<<dim3(64, 64), 256, FUSED_SMEM>>>(attn);

    out_gemm<<<dim3(8, 64), 256, GEMM_SMEM>>>(pC, WTo, bo, out);
}

// round 15
// speedup vs baseline: 1.1287x; 1.1287x over previous
#include <cuda_runtime.h>
#include <math.h>
#include <stdint.h>

#define B_  4
#define S_  2048
#define D_  1024
#define H_  16
#define HD_ 64
#define MS_ (B_*S_)   // 8192

// Scratch (static device globals — no allocation)
__device__ float g_Q[(size_t)MS_ * D_];
__device__ float g_K[(size_t)MS_ * D_];
__device__ float g_V[(size_t)MS_ * D_];
__device__ float g_VT[(size_t)B_ * H_ * HD_ * S_];   // V^T per head: [bh][hd][s]
__device__ float g_C[(size_t)MS_ * D_];
__device__ float g_WT[4][(size_t)D_ * D_];      // transposed + tf32-rounded weights

#define GEMM_SMEM  (512 * 36 * 4)                           // 73728 B
// fused (64q): Qs 64*68 | Ks 2*128*68 | Ls 64*4 | Rs 64 = 22080 floats
#define FUSED_SMEM ((64*68 + 256*68 + 64*4 + 64) * 4)       // 88320 B

// ---------------------------------------------------------------------------
// tf32 / cp.async helpers (sm_80+ ISA — compiles for plain sm_103 target)
// ---------------------------------------------------------------------------
__device__ __forceinline__ float f2tf(float f) {
    uint32_t u;
    asm("cvt.rna.tf32.f32 %0, %1;" : "=r"(u) : "f"(f));
    return __uint_as_float(u);
}

__device__ __forceinline__ void mma_tf32(float* d, const uint32_t* a, const uint32_t* b) {
    asm volatile(
        "mma.sync.aligned.m16n8k8.row.col.f32.tf32.tf32.f32 "
        "{%0,%1,%2,%3}, {%4,%5,%6,%7}, {%8,%9}, {%0,%1,%2,%3};"
        : "+f"(d[0]), "+f"(d[1]), "+f"(d[2]), "+f"(d[3])
        : "r"(a[0]), "r"(a[1]), "r"(a[2]), "r"(a[3]),
          "r"(b[0]), "r"(b[1]));
}

__device__ __forceinline__ uint32_t s32(const void* p) {
    return (uint32_t)__cvta_generic_to_shared(p);
}
__device__ __forceinline__ void cp_async16(uint32_t saddr, const void* gaddr) {
    asm volatile("cp.async.cg.shared.global [%0], [%1], 16;"
                 :: "r"(saddr), "l"(gaddr));
}
#define CP_COMMIT() asm volatile("cp.async.commit_group;")
#define CP_WAIT1()  asm volatile("cp.async.wait_group 1;")
#define CP_WAIT0()  asm volatile("cp.async.wait_group 0;")

// 128 rows x 32 cols chunk -> smem rows of stride 36 (256 threads)
__device__ __forceinline__ void cpB_chunk36(const float* G, int ld,
                                            uint32_t sbase, int tid) {
#pragma unroll
    for (int p = 0; p < 4; p++) {
        int f4 = p * 256 + tid;
        int r = f4 >> 3, c4 = (f4 & 7) * 4;
        cp_async16(sbase + (uint32_t)(r * 36 + c4) * 4, G + (size_t)r * ld + c4);
    }
}
// 64 rows x 32 cols chunk -> smem rows of stride 36 (256 threads)
__device__ __forceinline__ void cpV_chunk36(const float* G, int ld,
                                            uint32_t sbase, int tid) {
#pragma unroll
    for (int p = 0; p < 2; p++) {
        int f4 = p * 256 + tid;
        int r = f4 >> 3, c4 = (f4 & 7) * 4;
        cp_async16(sbase + (uint32_t)(r * 36 + c4) * 4, G + (size_t)r * ld + c4);
    }
}
// 128 rows x 64 cols tile -> smem rows of stride 68 (256 threads)
__device__ __forceinline__ void cpK_tile68(const float* G, int ld,
                                           uint32_t sbase, int tid) {
#pragma unroll
    for (int p = 0; p < 8; p++) {
        int f4 = p * 256 + tid;
        int r = f4 >> 4, c4 = (f4 & 15) * 4;
        cp_async16(sbase + (uint32_t)(r * 68 + c4) * 4, G + (size_t)r * ld + c4);
    }
}

// ===========================================================================
// Weight transposes (all 4 in one launch) + tf32 pre-round
// ===========================================================================
__global__ __launch_bounds__(256) void transpose4(
    const float* __restrict__ W0, const float* __restrict__ W1,
    const float* __restrict__ W2, const float* __restrict__ W3,
    float* __restrict__ O0, float* __restrict__ O1,
    float* __restrict__ O2, float* __restrict__ O3)
{
    int z = blockIdx.z;
    const float* in = (z == 0) ? W0 : (z == 1) ? W1 : (z == 2) ? W2 : W3;
    float* out      = (z == 0) ? O0 : (z == 1) ? O1 : (z == 2) ? O2 : O3;

    __shared__ float t[32][33];
    int x = blockIdx.x * 32 + threadIdx.x;
    int y = blockIdx.y * 32 + threadIdx.y;
#pragma unroll
    for (int j = 0; j < 32; j += 8)
        t[threadIdx.y + j][threadIdx.x] = in[(size_t)(y + j) * D_ + x];
    __syncthreads();
    x = blockIdx.y * 32 + threadIdx.x;
    y = blockIdx.x * 32 + threadIdx.y;
#pragma unroll
    for (int j = 0; j < 32; j += 8)
        out[(size_t)(y + j) * D_ + x] = f2tf(t[threadIdx.x][threadIdx.y + j]);
}

// ===========================================================================
// V per-head transpose: g_VT[bh][hd][s] = g_V[(b*S+s)][h*64+hd]
// ===========================================================================
__global__ __launch_bounds__(256) void vtrans(
    const float* __restrict__ V, float* __restrict__ VT)
{
    __shared__ float t[32][33];
    int bh = blockIdx.z;
    int b = bh >> 4, h = bh & 15;
    int s0 = blockIdx.x * 32, d0 = blockIdx.y * 32;
#pragma unroll
    for (int j = 0; j < 32; j += 8)
        t[threadIdx.y + j][threadIdx.x] =
            V[((size_t)b * S_ + s0 + threadIdx.y + j) * D_ + h * HD_ + d0 + threadIdx.x];
    __syncthreads();
#pragma unroll
    for (int j = 0; j < 32; j += 8)
        VT[((size_t)bh * HD_ + d0 + threadIdx.y + j) * S_ + s0 + threadIdx.x] =
            t[threadIdx.x][threadIdx.y + j];
}

// ===========================================================================
// 128x128xK MMA mainloop, BK=32: A via register prefetch + STS (optional cvt),
// B via cp.async 2-stage. As/Bs: 256 rows x 36 (two 128-row buffers each).
// ===========================================================================
template<bool CVTA>
__device__ __forceinline__ void gemm_main(
    const float* __restrict__ A, const float* __restrict__ BT,
    int K, int lda, int ldb,
    float (*As)[36], float (*Bs)[36],
    float (&acc)[4][4][4])
{
    int tid  = threadIdx.x;
    int lane = tid & 31, warp = tid >> 5;
    int g = lane >> 2, t = lane & 3;
    int wm = warp >> 2, wn = warp & 3;

    uint32_t sB = s32(Bs);
    const uint32_t BUFB = 128 * 36 * 4;
    int NT = K / 32;

    float4 pa[4];
#pragma unroll
    for (int p = 0; p < 4; p++) {
        int f4 = p * 256 + tid;
        int r = f4 >> 3, c4 = (f4 & 7) * 4;
        pa[p] = *(const float4*)(A + (size_t)r * lda + c4);
    }
    cpB_chunk36(BT, ldb, sB, tid); CP_COMMIT();
    if (NT > 1) { cpB_chunk36(BT + 32, ldb, sB + BUFB, tid); CP_COMMIT(); }

#pragma unroll
    for (int p = 0; p < 4; p++) {
        int f4 = p * 256 + tid;
        int r = f4 >> 3, c4 = (f4 & 7) * 4;
        As[r][c4 + 0] = CVTA ? f2tf(pa[p].x) : pa[p].x;
        As[r][c4 + 1] = CVTA ? f2tf(pa[p].y) : pa[p].y;
        As[r][c4 + 2] = CVTA ? f2tf(pa[p].z) : pa[p].z;
        As[r][c4 + 3] = CVTA ? f2tf(pa[p].w) : pa[p].w;
    }
    if (NT > 1) {
#pragma unroll
        for (int p = 0; p < 4; p++) {
            int f4 = p * 256 + tid;
            int r = f4 >> 3, c4 = (f4 & 7) * 4;
            pa[p] = *(const float4*)(A + (size_t)r * lda + 32 + c4);
        }
    }
    if (NT > 1) { CP_WAIT1(); } else { CP_WAIT0(); }
    __syncthreads();

    for (int it = 0; it < NT; it++) {
        int cur = (it & 1) * 128;
        if (it + 1 < NT) {
            int nb = ((it + 1) & 1) * 128;
#pragma unroll
            for (int p = 0; p < 4; p++) {
                int f4 = p * 256 + tid;
                int r = nb + (f4 >> 3), c4 = (f4 & 7) * 4;
                As[r][c4 + 0] = CVTA ? f2tf(pa[p].x) : pa[p].x;
                As[r][c4 + 1] = CVTA ? f2tf(pa[p].y) : pa[p].y;
                As[r][c4 + 2] = CVTA ? f2tf(pa[p].z) : pa[p].z;
                As[r][c4 + 3] = CVTA ? f2tf(pa[p].w) : pa[p].w;
            }
        }
        if (it + 2 < NT) {
            int k0 = (it + 2) * 32;
#pragma unroll
            for (int p = 0; p < 4; p++) {
                int f4 = p * 256 + tid;
                int r = f4 >> 3, c4 = (f4 & 7) * 4;
                pa[p] = *(const float4*)(A + (size_t)r * lda + k0 + c4);
            }
        }

#pragma unroll
        for (int kk = 0; kk < 32; kk += 8) {
            uint32_t af[4][4], bf[4][2];
#pragma unroll
            for (int mi = 0; mi < 4; mi++) {
                int mr = cur + wm * 64 + mi * 16 + g;
                af[mi][0] = __float_as_uint(As[mr][kk + t]);
                af[mi][1] = __float_as_uint(As[mr + 8][kk + t]);
                af[mi][2] = __float_as_uint(As[mr][kk + t + 4]);
                af[mi][3] = __float_as_uint(As[mr + 8][kk + t + 4]);
            }
#pragma unroll
            for (int ni = 0; ni < 4; ni++) {
                int nr = cur + wn * 32 + ni * 8 + g;
                bf[ni][0] = __float_as_uint(Bs[nr][kk + t]);
                bf[ni][1] = __float_as_uint(Bs[nr][kk + t + 4]);
            }
#pragma unroll
            for (int mi = 0; mi < 4; mi++)
#pragma unroll
                for (int ni = 0; ni < 4; ni++)
                    mma_tf32(acc[mi][ni], af[mi], bf[ni]);
        }
        __syncthreads();

        if (it + 2 < NT) {
            cpB_chunk36(BT + (it + 2) * 32, ldb,
                        sB + (uint32_t)(it & 1) * BUFB, tid);
            CP_COMMIT();
        }
        if (it + 1 < NT) {
            if (it + 2 < NT) { CP_WAIT1(); } else { CP_WAIT0(); }
            __syncthreads();
        }
    }
}

// ===========================================================================
// Fused Q/K/V projection GEMMs (grid.z selects tensor).
// ===========================================================================
__global__ __launch_bounds__(256, 2) void qkv_gemm(
    const float* __restrict__ Aq, const float* __restrict__ Ak,
    const float* __restrict__ Av,
    const float* __restrict__ Wq, const float* __restrict__ Wk,
    const float* __restrict__ Wv,
    const float* __restrict__ bq, const float* __restrict__ bk,
    const float* __restrict__ bv,
    float* __restrict__ Cq, float* __restrict__ Ck, float* __restrict__ Cv)
{
    extern __shared__ float sdyn[];
    float (*As)[36] = (float(*)[36])sdyn;         // 256 rows
    float (*Bs)[36] = (float(*)[36])sdyn + 256;   // 256 rows

    int z = blockIdx.z;
    const float* A    = (z == 0) ? Aq : (z == 1) ? Ak : Av;
    const float* BT   = (z == 0) ? Wq : (z == 1) ? Wk : Wv;
    const float* bias = (z == 0) ? bq : (z == 1) ? bk : bv;
    float*       C    = (z == 0) ? Cq : (z == 1) ? Ck : Cv;

    int m0 = blockIdx.y * 128, n0 = blockIdx.x * 128;

    float acc[4][4][4];
#pragma unroll
    for (int i = 0; i < 4; i++)
#pragma unroll
        for (int j = 0; j < 4; j++)
#pragma unroll
            for (int r = 0; r < 4; r++) acc[i][j][r] = 0.f;

    gemm_main<true>(A + (size_t)m0 * D_, BT + (size_t)n0 * D_,
                    D_, D_, D_, As, Bs, acc);

    int lane = threadIdx.x & 31, warp = threadIdx.x >> 5;
    int g = lane >> 2, t = lane & 3;
    int wm = warp >> 2, wn = warp & 3;
#pragma unroll
    for (int mi = 0; mi < 4; mi++) {
        int row = m0 + wm * 64 + mi * 16 + g;
#pragma unroll
        for (int ni = 0; ni < 4; ni++) {
            int col = n0 + wn * 32 + ni * 8 + 2 * t;
            float2 b2 = *(const float2*)(bias + col);
            float2 o0, o1;
            o0.x = f2tf(acc[mi][ni][0] + b2.x); o0.y = f2tf(acc[mi][ni][1] + b2.y);
            o1.x = f2tf(acc[mi][ni][2] + b2.x); o1.y = f2tf(acc[mi][ni][3] + b2.y);
            *(float2*)(C + (size_t)row * D_ + col)       = o0;
            *(float2*)(C + (size_t)(row + 8) * D_ + col) = o1;
        }
    }
}

// ===========================================================================
// Output projection GEMM.
// ===========================================================================
__global__ __launch_bounds__(256, 2) void out_gemm(
    const float* __restrict__ A, const float* __restrict__ BT,
    const float* __restrict__ bias, float* __restrict__ C)
{
    extern __shared__ float sdyn[];
    float (*As)[36] = (float(*)[36])sdyn;
    float (*Bs)[36] = (float(*)[36])sdyn + 256;

    int m0 = blockIdx.y * 128, n0 = blockIdx.x * 128;

    float acc[4][4][4];
#pragma unroll
    for (int i = 0; i < 4; i++)
#pragma unroll
        for (int j = 0; j < 4; j++)
#pragma unroll
            for (int r = 0; r < 4; r++) acc[i][j][r] = 0.f;

    gemm_main<false>(A + (size_t)m0 * D_, BT + (size_t)n0 * D_,
                     D_, D_, D_, As, Bs, acc);

    int lane = threadIdx.x & 31, warp = threadIdx.x >> 5;
    int g = lane >> 2, t = lane & 3;
    int wm = warp >> 2, wn = warp & 3;
#pragma unroll
    for (int mi = 0; mi < 4; mi++) {
        int row = m0 + wm * 64 + mi * 16 + g;
#pragma unroll
        for (int ni = 0; ni < 4; ni++) {
            int col = n0 + wn * 32 + ni * 8 + 2 * t;
            float2 b2 = *(const float2*)(bias + col);
            float2 o0, o1;
            o0.x = acc[mi][ni][0] + b2.x; o0.y = acc[mi][ni][1] + b2.y;
            o1.x = acc[mi][ni][2] + b2.x; o1.y = acc[mi][ni][3] + b2.y;
            *(float2*)(C + (size_t)row * D_ + col)       = o0;
            *(float2*)(C + (size_t)(row + 8) * D_ + col) = o1;
        }
    }
}

// ===========================================================================
// FUSED attention, 64-query strips: CTA = 64 q x 2048 k, one (b,h).
// Phase 1: E = exp(QK/8) -> attn, row sums -> smem rinv.
// Phase 2: E read back (mostly L2-hot), P = E*rinv overwrite, O = rinv*(E@V).
// grid (32, 64), 256 threads, 2 CTAs/SM, 88KB smem.
// ===========================================================================
__global__ __launch_bounds__(256, 2) void attn_fused(float* __restrict__ attn)
{
    extern __shared__ float sdyn[];
    // phase 1 layout
    float (*Qs)[68] = (float(*)[68])sdyn;                 // 64 rows
    float (*Ks)[68] = (float(*)[68])sdyn + 64;            // 256 rows (2 buf)
    float (*Ls)[4]  = (float(*)[4])(sdyn + 64*68 + 256*68);    // [64][4]
    float* Rs = sdyn + 64*68 + 256*68 + 64*4;             // 64 rinv
    // phase 2 layout (low region reused; Ls/Rs live above at 21760+)
    float (*As)[36] = (float(*)[36])sdyn;                 // 2 x 64 rows (4608)
    float (*Vs)[36] = (float(*)[36])sdyn + 128;           // 2 x 64 rows (4608)

    int tid  = threadIdx.x;
    int lane = tid & 31, warp = tid >> 5;
    int g = lane >> 2, t = lane & 3;

    int bh = blockIdx.y;
    int b = bh >> 4, h = bh & 15;
    int q0 = blockIdx.x * 64;

    const float* Qb = g_Q + ((size_t)b * S_ + q0) * D_ + h * HD_;
    const float* Kb = g_K + (size_t)b * S_ * D_ + h * HD_;
    float* Ab = attn + (size_t)bh * S_ * S_ + (size_t)q0 * S_;

    // ==================== Phase 1: E + row sums ====================
    {
        int wm = warp >> 2, wn = warp & 3;   // 2(m) x 4(n), warp tile 32q x 32k
        uint32_t sK = s32(Ks);
        const uint32_t BUFK = 128 * 68 * 4;

        cpK_tile68(Kb, D_, sK, tid); CP_COMMIT();
        cpK_tile68(Kb + (size_t)128 * D_, D_, sK + BUFK, tid); CP_COMMIT();

        // load Q tile 64 x 64 (pre-rounded tf32 in g_Q)
#pragma unroll
        for (int p = 0; p < 4; p++) {
            int f4 = p * 256 + tid;
            int r = f4 >> 4, c4 = (f4 & 15) * 4;
            *(float4*)(&Qs[r][c4]) = *(const float4*)(Qb + (size_t)r * D_ + c4);
        }

        float l4[4] = {0.f, 0.f, 0.f, 0.f};   // rows wm*32+mi*16+g(+8)

        CP_WAIT1();
        __syncthreads();

        const float scale = 0.125f;

        for (int kt = 0; kt < 16; kt++) {
            int cur = (kt & 1) * 128;

            float acc[2][4][4];
#pragma unroll
            for (int i = 0; i < 2; i++)
#pragma unroll
                for (int j = 0; j < 4; j++)
#pragma unroll
                    for (int r = 0; r < 4; r++) acc[i][j][r] = 0.f;

#pragma unroll
            for (int kk = 0; kk < 64; kk += 8) {
                uint32_t af[2][4], bf[4][2];
#pragma unroll
                for (int mi = 0; mi < 2; mi++) {
                    int mr = wm * 32 + mi * 16 + g;
                    af[mi][0] = __float_as_uint(Qs[mr][kk + t]);
                    af[mi][1] = __float_as_uint(Qs[mr + 8][kk + t]);
                    af[mi][2] = __float_as_uint(Qs[mr][kk + t + 4]);
                    af[mi][3] = __float_as_uint(Qs[mr + 8][kk + t + 4]);
                }
#pragma unroll
                for (int ni = 0; ni < 4; ni++) {
                    int nr = cur + wn * 32 + ni * 8 + g;
                    bf[ni][0] = __float_as_uint(Ks[nr][kk + t]);
                    bf[ni][1] = __float_as_uint(Ks[nr][kk + t + 4]);
                }
#pragma unroll
                for (int mi = 0; mi < 2; mi++)
#pragma unroll
                    for (int ni = 0; ni < 4; ni++)
                        mma_tf32(acc[mi][ni], af[mi], bf[ni]);
            }

#pragma unroll
            for (int mi = 0; mi < 2; mi++) {
                int row = wm * 32 + mi * 16 + g;
#pragma unroll
                for (int ni = 0; ni < 4; ni++) {
                    int col = kt * 128 + wn * 32 + ni * 8 + 2 * t;
#pragma unroll
                    for (int r = 0; r < 4; r++)
                        acc[mi][ni][r] = __expf(acc[mi][ni][r] * scale);
                    float2 o0, o1;
                    o0.x = acc[mi][ni][0]; o0.y = acc[mi][ni][1];
                    o1.x = acc[mi][ni][2]; o1.y = acc[mi][ni][3];
                    *(float2*)(Ab + (size_t)row * S_ + col)       = o0;
                    *(float2*)(Ab + (size_t)(row + 8) * S_ + col) = o1;
                    l4[mi * 2 + 0] += acc[mi][ni][0] + acc[mi][ni][1];
                    l4[mi * 2 + 1] += acc[mi][ni][2] + acc[mi][ni][3];
                }
            }
            __syncthreads();

            if (kt + 2 < 16) {
                cpK_tile68(Kb + (size_t)(kt + 2) * 128 * D_, D_,
                           sK + (uint32_t)(kt & 1) * BUFK, tid);
                CP_COMMIT();
            }
            if (kt + 1 < 16) {
                if (kt + 2 < 16) { CP_WAIT1(); } else { CP_WAIT0(); }
                __syncthreads();
            }
        }

        // reduce sums over quad lanes t (same rows)
#pragma unroll
        for (int i = 0; i < 4; i++) {
            float l = l4[i];
            l += __shfl_xor_sync(0xffffffffu, l, 1);
            l += __shfl_xor_sync(0xffffffffu, l, 2);
            l4[i] = l;
        }
        __syncthreads();   // phase-1 smem reads done before Ls writes
        if (t == 0) {
#pragma unroll
            for (int i = 0; i < 4; i++) {
                int mi = i >> 1, half = i & 1;
                int row = wm * 32 + mi * 16 + g + half * 8;
                Ls[row][wn] = l4[i];
            }
        }
        __syncthreads();
        if (tid < 64) {
            float l = Ls[tid][0] + Ls[tid][1] + Ls[tid][2] + Ls[tid][3];
            Rs[tid] = 1.0f / l;
        }
        __syncthreads();
    }

    // ==================== Phase 2: normalize + E @ V ====================
    {
        int wm = warp >> 1, wn = warp & 1;   // 4(m, 16 rows) x 2(n, 32 hd)
        const float* Vb = g_VT + (size_t)bh * HD_ * S_;   // [hd][s]
        uint32_t sV = s32(Vs);
        const uint32_t BUFV = 64 * 36 * 4;
        const int NT = S_ / 32;   // 64

        float acc[4][4];   // [ni][reg], warp tile 16 rows x 32 hd
#pragma unroll
        for (int j = 0; j < 4; j++)
#pragma unroll
            for (int r = 0; r < 4; r++) acc[j][r] = 0.f;

        float4 pa[2];   // 64 rows x 32 cols / 4 = 512 float4 -> 2 per thread
#pragma unroll
        for (int p = 0; p < 2; p++) {
            int f4 = p * 256 + tid;
            int r = f4 >> 3, c4 = (f4 & 7) * 4;
            pa[p] = *(const float4*)(Ab + (size_t)r * S_ + c4);
        }
        cpV_chunk36(Vb, S_, sV, tid); CP_COMMIT();
        cpV_chunk36(Vb + 32, S_, sV + BUFV, tid); CP_COMMIT();

        // transform + STS chunk 0 into As buf0 (+ final prob write p = e*rinv)
#pragma unroll
        for (int p = 0; p < 2; p++) {
            int f4 = p * 256 + tid;
            int r = f4 >> 3, c4 = (f4 & 7) * 4;
            float rv = Rs[r];
            float4 pr;
            pr.x = pa[p].x * rv; pr.y = pa[p].y * rv;
            pr.z = pa[p].z * rv; pr.w = pa[p].w * rv;
            *(float4*)(Ab + (size_t)r * S_ + c4) = pr;
            As[r][c4 + 0] = f2tf(pa[p].x); As[r][c4 + 1] = f2tf(pa[p].y);
            As[r][c4 + 2] = f2tf(pa[p].z); As[r][c4 + 3] = f2tf(pa[p].w);
        }
#pragma unroll
        for (int p = 0; p < 2; p++) {
            int f4 = p * 256 + tid;
            int r = f4 >> 3, c4 = (f4 & 7) * 4;
            pa[p] = *(const float4*)(Ab + (size_t)r * S_ + 32 + c4);
        }
        CP_WAIT1();
        __syncthreads();

        for (int it = 0; it < NT; it++) {
            int curA = (it & 1) * 64;
            int curV = (it & 1) * 64;
            if (it + 1 < NT) {
                int nb = ((it + 1) & 1) * 64;
                int kb = (it + 1) * 32;
#pragma unroll
                for (int p = 0; p < 2; p++) {
                    int f4 = p * 256 + tid;
                    int r = f4 >> 3, c4 = (f4 & 7) * 4;
                    float rv = Rs[r];
                    float4 pr;
                    pr.x = pa[p].x * rv; pr.y = pa[p].y * rv;
                    pr.z = pa[p].z * rv; pr.w = pa[p].w * rv;
                    *(float4*)(Ab + (size_t)r * S_ + kb + c4) = pr;
                    As[nb + r][c4 + 0] = f2tf(pa[p].x);
                    As[nb + r][c4 + 1] = f2tf(pa[p].y);
                    As[nb + r][c4 + 2] = f2tf(pa[p].z);
                    As[nb + r][c4 + 3] = f2tf(pa[p].w);
                }
            }
            if (it + 2 < NT) {
                int k0 = (it + 2) * 32;
#pragma unroll
                for (int p = 0; p < 2; p++) {
                    int f4 = p * 256 + tid;
                    int r = f4 >> 3, c4 = (f4 & 7) * 4;
                    pa[p] = *(const float4*)(Ab + (size_t)r * S_ + k0 + c4);
                }
            }

#pragma unroll
            for (int kk = 0; kk < 32; kk += 8) {
                uint32_t af[4], bf[4][2];
                int mr = curA + wm * 16 + g;
                af[0] = __float_as_uint(As[mr][kk + t]);
                af[1] = __float_as_uint(As[mr + 8][kk + t]);
                af[2] = __float_as_uint(As[mr][kk + t + 4]);
                af[3] = __float_as_uint(As[mr + 8][kk + t + 4]);
#pragma unroll
                for (int ni = 0; ni < 4; ni++) {
                    int nr = curV + wn * 32 + ni * 8 + g;
                    bf[ni][0] = __float_as_uint(Vs[nr][kk + t]);
                    bf[ni][1] = __float_as_uint(Vs[nr][kk + t + 4]);
                }
#pragma unroll
                for (int ni = 0; ni < 4; ni++)
                    mma_tf32(acc[ni], af, bf[ni]);
            }
            __syncthreads();

            if (it + 2 < NT) {
                cpV_chunk36(Vb + (it + 2) * 32, S_,
                            sV + (uint32_t)(it & 1) * BUFV, tid);
                CP_COMMIT();
            }
            if (it + 1 < NT) {
                if (it + 2 < NT) { CP_WAIT1(); } else { CP_WAIT0(); }
                __syncthreads();
            }
        }

        // epilogue: O = rinv_row * acc
        float* Cb = g_C + ((size_t)b * S_ + q0) * D_ + h * HD_;
        int row = wm * 16 + g;
        float rv0 = Rs[row], rv1 = Rs[row + 8];
#pragma unroll
        for (int ni = 0; ni < 4; ni++) {
            int col = wn * 32 + ni * 8 + 2 * t;
            float2 o0, o1;
            o0.x = f2tf(acc[ni][0] * rv0); o0.y = f2tf(acc[ni][1] * rv0);
            o1.x = f2tf(acc[ni][2] * rv1); o1.y = f2tf(acc[ni][3] * rv1);
            *(float2*)(Cb + (size_t)row * D_ + col)       = o0;
            *(float2*)(Cb + (size_t)(row + 8) * D_ + col) = o1;
        }
    }
}

// ---------------------------------------------------------------------------
extern "C" void kernel_launch(void* const* d_in, const int* in_sizes, int n_in,
                              void* d_out, int out_size)
{
    const float* q  = (const float*)d_in[0];
    const float* k  = (const float*)d_in[1];
    const float* v  = (const float*)d_in[2];
    const float* Wq = (const float*)d_in[3];
    const float* bq = (const float*)d_in[4];
    const float* Wk = (const float*)d_in[5];
    const float* bk = (const float*)d_in[6];
    const float* Wv = (const float*)d_in[7];
    const float* bv = (const float*)d_in[8];
    const float* Wo = (const float*)d_in[9];
    const float* bo = (const float*)d_in[10];

    float* out  = (float*)d_out;
    float* attn = out + (size_t)MS_ * D_;   // tuple order: (output, attention)

    float *pQ, *pK, *pV, *pVT, *pC, *pWT;
    cudaGetSymbolAddress((void**)&pQ, g_Q);
    cudaGetSymbolAddress((void**)&pK, g_K);
    cudaGetSymbolAddress((void**)&pV, g_V);
    cudaGetSymbolAddress((void**)&pVT, g_VT);
    cudaGetSymbolAddress((void**)&pC, g_C);
    cudaGetSymbolAddress((void**)&pWT, g_WT);

    cudaFuncSetAttribute(qkv_gemm,
                         cudaFuncAttributeMaxDynamicSharedMemorySize, GEMM_SMEM);
    cudaFuncSetAttribute(out_gemm,
                         cudaFuncAttributeMaxDynamicSharedMemorySize, GEMM_SMEM);
    cudaFuncSetAttribute(attn_fused,
                         cudaFuncAttributeMaxDynamicSharedMemorySize, FUSED_SMEM);

    float* WTq = pWT + 0 * (size_t)D_ * D_;
    float* WTk = pWT + 1 * (size_t)D_ * D_;
    float* WTv = pWT + 2 * (size_t)D_ * D_;
    float* WTo = pWT + 3 * (size_t)D_ * D_;

    transpose4<<<dim3(32, 32, 4), dim3(32, 8)>>>(Wq, Wk, Wv, Wo,
                                                 WTq, WTk, WTv, WTo);

    qkv_gemm<<<dim3(8, 64, 3), 256, GEMM_SMEM>>>(q, k, v, WTq, WTk, WTv,
                                                 bq, bk, bv, pQ, pK, pV);

    vtrans<<<dim3(64, 2, 64), dim3(32, 8)>>>(pV, pVT);

    attn_fused<<<dim3(32, 64), 256, FUSED_SMEM>>>(attn);

    out_gemm<<<dim3(8, 64), 256, GEMM_SMEM>>>(pC, WTo, bo, out);
}

// round 16
// speedup vs baseline: 1.1913x; 1.0554x over previous
#include <cuda_runtime.h>
#include <cuda_fp16.h>
#include <math.h>
#include <stdint.h>

#define B_  4
#define S_  2048
#define D_  1024
#define H_  16
#define HD_ 64
#define MS_ (B_*S_)   // 8192

// Scratch (static device globals — no allocation)
__device__ float g_Q[(size_t)MS_ * D_];
__device__ float g_K[(size_t)MS_ * D_];
__device__ float g_V[(size_t)MS_ * D_];
__device__ float g_VT[(size_t)B_ * H_ * HD_ * S_];   // V^T per head: [bh][hd][s]
__device__ float g_C[(size_t)MS_ * D_];
__device__ float g_WT[4][(size_t)D_ * D_];      // transposed + tf32-rounded weights

#define GEMM_SMEM  (512 * 36 * 4)                       // 73728 B
#define FUSED_SMEM ((128*68 + 256*68 + 128*4) * 4)      // 106496 B

// ---------------------------------------------------------------------------
// tf32 / cp.async helpers (sm_80+ ISA — compiles for plain sm_103 target)
// ---------------------------------------------------------------------------
__device__ __forceinline__ float f2tf(float f) {
    uint32_t u;
    asm("cvt.rna.tf32.f32 %0, %1;" : "=r"(u) : "f"(f));
    return __uint_as_float(u);
}

__device__ __forceinline__ void mma_tf32(float* d, const uint32_t* a, const uint32_t* b) {
    asm volatile(
        "mma.sync.aligned.m16n8k8.row.col.f32.tf32.tf32.f32 "
        "{%0,%1,%2,%3}, {%4,%5,%6,%7}, {%8,%9}, {%0,%1,%2,%3};"
        : "+f"(d[0]), "+f"(d[1]), "+f"(d[2]), "+f"(d[3])
        : "r"(a[0]), "r"(a[1]), "r"(a[2]), "r"(a[3]),
          "r"(b[0]), "r"(b[1]));
}

__device__ __forceinline__ uint32_t s32(const void* p) {
    return (uint32_t)__cvta_generic_to_shared(p);
}
__device__ __forceinline__ void cp_async16(uint32_t saddr, const void* gaddr) {
    asm volatile("cp.async.cg.shared.global [%0], [%1], 16;"
                 :: "r"(saddr), "l"(gaddr));
}
#define CP_COMMIT() asm volatile("cp.async.commit_group;")
#define CP_WAIT1()  asm volatile("cp.async.wait_group 1;")
#define CP_WAIT0()  asm volatile("cp.async.wait_group 0;")

// 128 rows x 32 cols chunk -> smem rows of stride 36 (256 threads)
__device__ __forceinline__ void cpB_chunk36(const float* G, int ld,
                                            uint32_t sbase, int tid) {
#pragma unroll
    for (int p = 0; p < 4; p++) {
        int f4 = p * 256 + tid;
        int r = f4 >> 3, c4 = (f4 & 7) * 4;
        cp_async16(sbase + (uint32_t)(r * 36 + c4) * 4, G + (size_t)r * ld + c4);
    }
}
// 64 rows x 32 cols chunk -> smem rows of stride 36 (256 threads)
__device__ __forceinline__ void cpV_chunk36(const float* G, int ld,
                                            uint32_t sbase, int tid) {
#pragma unroll
    for (int p = 0; p < 2; p++) {
        int f4 = p * 256 + tid;
        int r = f4 >> 3, c4 = (f4 & 7) * 4;
        cp_async16(sbase + (uint32_t)(r * 36 + c4) * 4, G + (size_t)r * ld + c4);
    }
}
// 128 rows x 64 cols tile -> smem rows of stride 68 (256 threads)
__device__ __forceinline__ void cpK_tile68(const float* G, int ld,
                                           uint32_t sbase, int tid) {
#pragma unroll
    for (int p = 0; p < 8; p++) {
        int f4 = p * 256 + tid;
        int r = f4 >> 4, c4 = (f4 & 15) * 4;
        cp_async16(sbase + (uint32_t)(r * 68 + c4) * 4, G + (size_t)r * ld + c4);
    }
}

// ===========================================================================
// Weight transposes (all 4 in one launch) + tf32 pre-round
// ===========================================================================
__global__ __launch_bounds__(256) void transpose4(
    const float* __restrict__ W0, const float* __restrict__ W1,
    const float* __restrict__ W2, const float* __restrict__ W3,
    float* __restrict__ O0, float* __restrict__ O1,
    float* __restrict__ O2, float* __restrict__ O3)
{
    int z = blockIdx.z;
    const float* in = (z == 0) ? W0 : (z == 1) ? W1 : (z == 2) ? W2 : W3;
    float* out      = (z == 0) ? O0 : (z == 1) ? O1 : (z == 2) ? O2 : O3;

    __shared__ float t[32][33];
    int x = blockIdx.x * 32 + threadIdx.x;
    int y = blockIdx.y * 32 + threadIdx.y;
#pragma unroll
    for (int j = 0; j < 32; j += 8)
        t[threadIdx.y + j][threadIdx.x] = in[(size_t)(y + j) * D_ + x];
    __syncthreads();
    x = blockIdx.y * 32 + threadIdx.x;
    y = blockIdx.x * 32 + threadIdx.y;
#pragma unroll
    for (int j = 0; j < 32; j += 8)
        out[(size_t)(y + j) * D_ + x] = f2tf(t[threadIdx.x][threadIdx.y + j]);
}

// ===========================================================================
// V per-head transpose: g_VT[bh][hd][s] = g_V[(b*S+s)][h*64+hd]
// ===========================================================================
__global__ __launch_bounds__(256) void vtrans(
    const float* __restrict__ V, float* __restrict__ VT)
{
    __shared__ float t[32][33];
    int bh = blockIdx.z;
    int b = bh >> 4, h = bh & 15;
    int s0 = blockIdx.x * 32, d0 = blockIdx.y * 32;
#pragma unroll
    for (int j = 0; j < 32; j += 8)
        t[threadIdx.y + j][threadIdx.x] =
            V[((size_t)b * S_ + s0 + threadIdx.y + j) * D_ + h * HD_ + d0 + threadIdx.x];
    __syncthreads();
#pragma unroll
    for (int j = 0; j < 32; j += 8)
        VT[((size_t)bh * HD_ + d0 + threadIdx.y + j) * S_ + s0 + threadIdx.x] =
            t[threadIdx.x][threadIdx.y + j];
}

// ===========================================================================
// 128x128xK MMA mainloop, BK=32: A via register prefetch + STS (optional cvt),
// B via cp.async 2-stage. As/Bs: 256 rows x 36 (two 128-row buffers each).
// ===========================================================================
template<bool CVTA>
__device__ __forceinline__ void gemm_main(
    const float* __restrict__ A, const float* __restrict__ BT,
    int K, int lda, int ldb,
    float (*As)[36], float (*Bs)[36],
    float (&acc)[4][4][4])
{
    int tid  = threadIdx.x;
    int lane = tid & 31, warp = tid >> 5;
    int g = lane >> 2, t = lane & 3;
    int wm = warp >> 2, wn = warp & 3;

    uint32_t sB = s32(Bs);
    const uint32_t BUFB = 128 * 36 * 4;
    int NT = K / 32;

    float4 pa[4];
#pragma unroll
    for (int p = 0; p < 4; p++) {
        int f4 = p * 256 + tid;
        int r = f4 >> 3, c4 = (f4 & 7) * 4;
        pa[p] = *(const float4*)(A + (size_t)r * lda + c4);
    }
    cpB_chunk36(BT, ldb, sB, tid); CP_COMMIT();
    if (NT > 1) { cpB_chunk36(BT + 32, ldb, sB + BUFB, tid); CP_COMMIT(); }

#pragma unroll
    for (int p = 0; p < 4; p++) {
        int f4 = p * 256 + tid;
        int r = f4 >> 3, c4 = (f4 & 7) * 4;
        As[r][c4 + 0] = CVTA ? f2tf(pa[p].x) : pa[p].x;
        As[r][c4 + 1] = CVTA ? f2tf(pa[p].y) : pa[p].y;
        As[r][c4 + 2] = CVTA ? f2tf(pa[p].z) : pa[p].z;
        As[r][c4 + 3] = CVTA ? f2tf(pa[p].w) : pa[p].w;
    }
    if (NT > 1) {
#pragma unroll
        for (int p = 0; p < 4; p++) {
            int f4 = p * 256 + tid;
            int r = f4 >> 3, c4 = (f4 & 7) * 4;
            pa[p] = *(const float4*)(A + (size_t)r * lda + 32 + c4);
        }
    }
    if (NT > 1) { CP_WAIT1(); } else { CP_WAIT0(); }
    __syncthreads();

    for (int it = 0; it < NT; it++) {
        int cur = (it & 1) * 128;
        if (it + 1 < NT) {
            int nb = ((it + 1) & 1) * 128;
#pragma unroll
            for (int p = 0; p < 4; p++) {
                int f4 = p * 256 + tid;
                int r = nb + (f4 >> 3), c4 = (f4 & 7) * 4;
                As[r][c4 + 0] = CVTA ? f2tf(pa[p].x) : pa[p].x;
                As[r][c4 + 1] = CVTA ? f2tf(pa[p].y) : pa[p].y;
                As[r][c4 + 2] = CVTA ? f2tf(pa[p].z) : pa[p].z;
                As[r][c4 + 3] = CVTA ? f2tf(pa[p].w) : pa[p].w;
            }
        }
        if (it + 2 < NT) {
            int k0 = (it + 2) * 32;
#pragma unroll
            for (int p = 0; p < 4; p++) {
                int f4 = p * 256 + tid;
                int r = f4 >> 3, c4 = (f4 & 7) * 4;
                pa[p] = *(const float4*)(A + (size_t)r * lda + k0 + c4);
            }
        }

#pragma unroll
        for (int kk = 0; kk < 32; kk += 8) {
            uint32_t af[4][4], bf[4][2];
#pragma unroll
            for (int mi = 0; mi < 4; mi++) {
                int mr = cur + wm * 64 + mi * 16 + g;
                af[mi][0] = __float_as_uint(As[mr][kk + t]);
                af[mi][1] = __float_as_uint(As[mr + 8][kk + t]);
                af[mi][2] = __float_as_uint(As[mr][kk + t + 4]);
                af[mi][3] = __float_as_uint(As[mr + 8][kk + t + 4]);
            }
#pragma unroll
            for (int ni = 0; ni < 4; ni++) {
                int nr = cur + wn * 32 + ni * 8 + g;
                bf[ni][0] = __float_as_uint(Bs[nr][kk + t]);
                bf[ni][1] = __float_as_uint(Bs[nr][kk + t + 4]);
            }
#pragma unroll
            for (int mi = 0; mi < 4; mi++)
#pragma unroll
                for (int ni = 0; ni < 4; ni++)
                    mma_tf32(acc[mi][ni], af[mi], bf[ni]);
        }
        __syncthreads();

        if (it + 2 < NT) {
            cpB_chunk36(BT + (it + 2) * 32, ldb,
                        sB + (uint32_t)(it & 1) * BUFB, tid);
            CP_COMMIT();
        }
        if (it + 1 < NT) {
            if (it + 2 < NT) { CP_WAIT1(); } else { CP_WAIT0(); }
            __syncthreads();
        }
    }
}

// ===========================================================================
// Fused Q/K/V projection GEMMs (grid.z selects tensor).
// ===========================================================================
__global__ __launch_bounds__(256, 2) void qkv_gemm(
    const float* __restrict__ Aq, const float* __restrict__ Ak,
    const float* __restrict__ Av,
    const float* __restrict__ Wq, const float* __restrict__ Wk,
    const float* __restrict__ Wv,
    const float* __restrict__ bq, const float* __restrict__ bk,
    const float* __restrict__ bv,
    float* __restrict__ Cq, float* __restrict__ Ck, float* __restrict__ Cv)
{
    extern __shared__ float sdyn[];
    float (*As)[36] = (float(*)[36])sdyn;         // 256 rows
    float (*Bs)[36] = (float(*)[36])sdyn + 256;   // 256 rows

    int z = blockIdx.z;
    const float* A    = (z == 0) ? Aq : (z == 1) ? Ak : Av;
    const float* BT   = (z == 0) ? Wq : (z == 1) ? Wk : Wv;
    const float* bias = (z == 0) ? bq : (z == 1) ? bk : bv;
    float*       C    = (z == 0) ? Cq : (z == 1) ? Ck : Cv;

    int m0 = blockIdx.y * 128, n0 = blockIdx.x * 128;

    float acc[4][4][4];
#pragma unroll
    for (int i = 0; i < 4; i++)
#pragma unroll
        for (int j = 0; j < 4; j++)
#pragma unroll
            for (int r = 0; r < 4; r++) acc[i][j][r] = 0.f;

    gemm_main<true>(A + (size_t)m0 * D_, BT + (size_t)n0 * D_,
                    D_, D_, D_, As, Bs, acc);

    int lane = threadIdx.x & 31, warp = threadIdx.x >> 5;
    int g = lane >> 2, t = lane & 3;
    int wm = warp >> 2, wn = warp & 3;
#pragma unroll
    for (int mi = 0; mi < 4; mi++) {
        int row = m0 + wm * 64 + mi * 16 + g;
#pragma unroll
        for (int ni = 0; ni < 4; ni++) {
            int col = n0 + wn * 32 + ni * 8 + 2 * t;
            float2 b2 = *(const float2*)(bias + col);
            float2 o0, o1;
            o0.x = f2tf(acc[mi][ni][0] + b2.x); o0.y = f2tf(acc[mi][ni][1] + b2.y);
            o1.x = f2tf(acc[mi][ni][2] + b2.x); o1.y = f2tf(acc[mi][ni][3] + b2.y);
            *(float2*)(C + (size_t)row * D_ + col)       = o0;
            *(float2*)(C + (size_t)(row + 8) * D_ + col) = o1;
        }
    }
}

// ===========================================================================
// Output projection GEMM.
// ===========================================================================
__global__ __launch_bounds__(256, 2) void out_gemm(
    const float* __restrict__ A, const float* __restrict__ BT,
    const float* __restrict__ bias, float* __restrict__ C)
{
    extern __shared__ float sdyn[];
    float (*As)[36] = (float(*)[36])sdyn;
    float (*Bs)[36] = (float(*)[36])sdyn + 256;

    int m0 = blockIdx.y * 128, n0 = blockIdx.x * 128;

    float acc[4][4][4];
#pragma unroll
    for (int i = 0; i < 4; i++)
#pragma unroll
        for (int j = 0; j < 4; j++)
#pragma unroll
            for (int r = 0; r < 4; r++) acc[i][j][r] = 0.f;

    gemm_main<false>(A + (size_t)m0 * D_, BT + (size_t)n0 * D_,
                     D_, D_, D_, As, Bs, acc);

    int lane = threadIdx.x & 31, warp = threadIdx.x >> 5;
    int g = lane >> 2, t = lane & 3;
    int wm = warp >> 2, wn = warp & 3;
#pragma unroll
    for (int mi = 0; mi < 4; mi++) {
        int row = m0 + wm * 64 + mi * 16 + g;
#pragma unroll
        for (int ni = 0; ni < 4; ni++) {
            int col = n0 + wn * 32 + ni * 8 + 2 * t;
            float2 b2 = *(const float2*)(bias + col);
            float2 o0, o1;
            o0.x = acc[mi][ni][0] + b2.x; o0.y = acc[mi][ni][1] + b2.y;
            o1.x = acc[mi][ni][2] + b2.x; o1.y = acc[mi][ni][3] + b2.y;
            *(float2*)(C + (size_t)row * D_ + col)       = o0;
            *(float2*)(C + (size_t)(row + 8) * D_ + col) = o1;
        }
    }
}

// ===========================================================================
// FUSED attention: CTA = 128 queries x all 2048 keys for one (b,h).
// Phase 1: E = exp(QK/8) stored as fp16 packed into the UPPER HALF of each
//          attn row (fp32 slots [1024,2048)); row sums -> smem rinv.
// Phase 2: read fp16 E ascending, write fp32 P = E*rinv into slots [0,2048)
//          (ascending writes never clobber unread E: P chunk c destroys E
//          elements < 64c-1984, all read >= 2 chunks earlier), O = rinv*(E@V).
// Halves E round-trip DRAM traffic. grid (16, 64), 256 thr, 2 CTAs/SM.
// ===========================================================================
__global__ __launch_bounds__(256, 2) void attn_fused(float* __restrict__ attn)
{
    extern __shared__ float sdyn[];
    // phase 1 layout
    float (*Qs)[68] = (float(*)[68])sdyn;                 // 128 rows
    float (*Ks)[68] = (float(*)[68])sdyn + 128;           // 256 rows (2 buf)
    float (*Ls)[4]  = (float(*)[4])(sdyn + 128*68 + 256*68);   // [128][4]
    // phase 2 layout (reuses the same memory after phase 1 completes)
    float (*As)[36] = (float(*)[36])sdyn;                 // 2 x 128 rows
    float (*Vs)[36] = (float(*)[36])sdyn + 256;           // 2 x 64 rows
    float* Rs = sdyn + 256 * 36 + 128 * 36;               // 128 rinv

    int tid  = threadIdx.x;
    int lane = tid & 31, warp = tid >> 5;
    int g = lane >> 2, t = lane & 3;

    int bh = blockIdx.y;
    int b = bh >> 4, h = bh & 15;
    int q0 = blockIdx.x * 128;

    const float* Qb = g_Q + ((size_t)b * S_ + q0) * D_ + h * HD_;
    const float* Kb = g_K + (size_t)b * S_ * D_ + h * HD_;
    float* Ab = attn + (size_t)bh * S_ * S_ + (size_t)q0 * S_;

    // ==================== Phase 1: E (fp16) + row sums ====================
    {
        int wm = warp >> 2, wn = warp & 3;
        uint32_t sK = s32(Ks);
        const uint32_t BUFK = 128 * 68 * 4;

        cpK_tile68(Kb, D_, sK, tid); CP_COMMIT();
        cpK_tile68(Kb + (size_t)128 * D_, D_, sK + BUFK, tid); CP_COMMIT();

#pragma unroll
        for (int p = 0; p < 8; p++) {
            int f4 = p * 256 + tid;
            int r = f4 >> 4, c4 = (f4 & 15) * 4;
            *(float4*)(&Qs[r][c4]) = *(const float4*)(Qb + (size_t)r * D_ + c4);
        }

        float l8[8];
#pragma unroll
        for (int i = 0; i < 8; i++) l8[i] = 0.f;

        CP_WAIT1();
        __syncthreads();

        const float scale = 0.125f;

        for (int kt = 0; kt < 16; kt++) {
            int cur = (kt & 1) * 128;

            float acc[4][4][4];
#pragma unroll
            for (int i = 0; i < 4; i++)
#pragma unroll
                for (int j = 0; j < 4; j++)
#pragma unroll
                    for (int r = 0; r < 4; r++) acc[i][j][r] = 0.f;

#pragma unroll
            for (int kk = 0; kk < 64; kk += 8) {
                uint32_t af[4][4], bf[4][2];
#pragma unroll
                for (int mi = 0; mi < 4; mi++) {
                    int mr = wm * 64 + mi * 16 + g;
                    af[mi][0] = __float_as_uint(Qs[mr][kk + t]);
                    af[mi][1] = __float_as_uint(Qs[mr + 8][kk + t]);
                    af[mi][2] = __float_as_uint(Qs[mr][kk + t + 4]);
                    af[mi][3] = __float_as_uint(Qs[mr + 8][kk + t + 4]);
                }
#pragma unroll
                for (int ni = 0; ni < 4; ni++) {
                    int nr = cur + wn * 32 + ni * 8 + g;
                    bf[ni][0] = __float_as_uint(Ks[nr][kk + t]);
                    bf[ni][1] = __float_as_uint(Ks[nr][kk + t + 4]);
                }
#pragma unroll
                for (int mi = 0; mi < 4; mi++)
#pragma unroll
                    for (int ni = 0; ni < 4; ni++)
                        mma_tf32(acc[mi][ni], af[mi], bf[ni]);
            }

#pragma unroll
            for (int mi = 0; mi < 4; mi++) {
                int row = wm * 64 + mi * 16 + g;
                __half2* hrow0 = (__half2*)(Ab + (size_t)row * S_ + 1024);
                __half2* hrow1 = (__half2*)(Ab + (size_t)(row + 8) * S_ + 1024);
#pragma unroll
                for (int ni = 0; ni < 4; ni++) {
                    int col = kt * 128 + wn * 32 + ni * 8 + 2 * t;
#pragma unroll
                    for (int r = 0; r < 4; r++)
                        acc[mi][ni][r] = __expf(acc[mi][ni][r] * scale);
                    hrow0[col >> 1] = __floats2half2_rn(acc[mi][ni][0], acc[mi][ni][1]);
                    hrow1[col >> 1] = __floats2half2_rn(acc[mi][ni][2], acc[mi][ni][3]);
                    l8[mi * 2 + 0] += acc[mi][ni][0] + acc[mi][ni][1];
                    l8[mi * 2 + 1] += acc[mi][ni][2] + acc[mi][ni][3];
                }
            }
            __syncthreads();

            if (kt + 2 < 16) {
                cpK_tile68(Kb + (size_t)(kt + 2) * 128 * D_, D_,
                           sK + (uint32_t)(kt & 1) * BUFK, tid);
                CP_COMMIT();
            }
            if (kt + 1 < 16) {
                if (kt + 2 < 16) { CP_WAIT1(); } else { CP_WAIT0(); }
                __syncthreads();
            }
        }

        // reduce sums over quad lanes t (same rows)
#pragma unroll
        for (int ti = 0; ti < 8; ti++) {
            float l = l8[ti];
            l += __shfl_xor_sync(0xffffffffu, l, 1);
            l += __shfl_xor_sync(0xffffffffu, l, 2);
            l8[ti] = l;
        }
        __syncthreads();   // phase-1 smem reads done before Ls writes
        if (t == 0) {
#pragma unroll
            for (int ti = 0; ti < 8; ti++) {
                int mi = ti >> 1, half = ti & 1;
                int row = wm * 64 + mi * 16 + g + half * 8;
                Ls[row][wn] = l8[ti];
            }
        }
        __syncthreads();
        if (tid < 128) {
            float l = Ls[tid][0] + Ls[tid][1] + Ls[tid][2] + Ls[tid][3];
            Rs[tid] = 1.0f / l;
        }
        __syncthreads();
    }

    // ==================== Phase 2: normalize + E @ V ====================
    {
        int wm = warp >> 1, wn = warp & 1;   // 4 x 2
        const float* Vb = g_VT + (size_t)bh * HD_ * S_;   // [hd][s]
        uint32_t sV = s32(Vs);
        const uint32_t BUFV = 64 * 36 * 4;
        const int NT = S_ / 32;   // 64

        float acc[2][4][4];
#pragma unroll
        for (int i = 0; i < 2; i++)
#pragma unroll
            for (int j = 0; j < 4; j++)
#pragma unroll
                for (int r = 0; r < 4; r++) acc[i][j][r] = 0.f;

        float4 pa[4];
        // E chunk 0 -> regs (fp16 upper-half read) ; V chunks 0,1 -> cp.async
#pragma unroll
        for (int p = 0; p < 4; p++) {
            int f4 = p * 256 + tid;
            int r = f4 >> 3, c4 = (f4 & 7) * 4;
            const __half* hp = (const __half*)(Ab + (size_t)r * S_ + 1024);
            uint2 raw = *(const uint2*)(hp + c4);
            float2 f0 = __half22float2(*(__half2*)&raw.x);
            float2 f1 = __half22float2(*(__half2*)&raw.y);
            pa[p] = make_float4(f0.x, f0.y, f1.x, f1.y);
        }
        cpV_chunk36(Vb, S_, sV, tid); CP_COMMIT();
        cpV_chunk36(Vb + 32, S_, sV + BUFV, tid); CP_COMMIT();

        // transform + STS chunk 0 into As buf0 (+ final prob write p = e*rinv)
#pragma unroll
        for (int p = 0; p < 4; p++) {
            int f4 = p * 256 + tid;
            int r = f4 >> 3, c4 = (f4 & 7) * 4;
            float rv = Rs[r];
            float4 pr;
            pr.x = pa[p].x * rv; pr.y = pa[p].y * rv;
            pr.z = pa[p].z * rv; pr.w = pa[p].w * rv;
            *(float4*)(Ab + (size_t)r * S_ + c4) = pr;
            As[r][c4 + 0] = f2tf(pa[p].x); As[r][c4 + 1] = f2tf(pa[p].y);
            As[r][c4 + 2] = f2tf(pa[p].z); As[r][c4 + 3] = f2tf(pa[p].w);
        }
#pragma unroll
        for (int p = 0; p < 4; p++) {
            int f4 = p * 256 + tid;
            int r = f4 >> 3, c4 = (f4 & 7) * 4;
            const __half* hp = (const __half*)(Ab + (size_t)r * S_ + 1024);
            uint2 raw = *(const uint2*)(hp + 32 + c4);
            float2 f0 = __half22float2(*(__half2*)&raw.x);
            float2 f1 = __half22float2(*(__half2*)&raw.y);
            pa[p] = make_float4(f0.x, f0.y, f1.x, f1.y);
        }
        CP_WAIT1();
        __syncthreads();

        for (int it = 0; it < NT; it++) {
            int curA = (it & 1) * 128;
            int curV = (it & 1) * 64;
            if (it + 1 < NT) {
                int nb = ((it + 1) & 1) * 128;
                int kb = (it + 1) * 32;
#pragma unroll
                for (int p = 0; p < 4; p++) {
                    int f4 = p * 256 + tid;
                    int r = f4 >> 3, c4 = (f4 & 7) * 4;
                    float rv = Rs[r];
                    float4 pr;
                    pr.x = pa[p].x * rv; pr.y = pa[p].y * rv;
                    pr.z = pa[p].z * rv; pr.w = pa[p].w * rv;
                    *(float4*)(Ab + (size_t)r * S_ + kb + c4) = pr;
                    As[nb + r][c4 + 0] = f2tf(pa[p].x);
                    As[nb + r][c4 + 1] = f2tf(pa[p].y);
                    As[nb + r][c4 + 2] = f2tf(pa[p].z);
                    As[nb + r][c4 + 3] = f2tf(pa[p].w);
                }
            }
            if (it + 2 < NT) {
                int k0 = (it + 2) * 32;
#pragma unroll
                for (int p = 0; p < 4; p++) {
                    int f4 = p * 256 + tid;
                    int r = f4 >> 3, c4 = (f4 & 7) * 4;
                    const __half* hp = (const __half*)(Ab + (size_t)r * S_ + 1024);
                    uint2 raw = *(const uint2*)(hp + k0 + c4);
                    float2 f0 = __half22float2(*(__half2*)&raw.x);
                    float2 f1 = __half22float2(*(__half2*)&raw.y);
                    pa[p] = make_float4(f0.x, f0.y, f1.x, f1.y);
                }
            }

#pragma unroll
            for (int kk = 0; kk < 32; kk += 8) {
                uint32_t af[2][4], bf[4][2];
#pragma unroll
                for (int mi = 0; mi < 2; mi++) {
                    int mr = curA + wm * 32 + mi * 16 + g;
                    af[mi][0] = __float_as_uint(As[mr][kk + t]);
                    af[mi][1] = __float_as_uint(As[mr + 8][kk + t]);
                    af[mi][2] = __float_as_uint(As[mr][kk + t + 4]);
                    af[mi][3] = __float_as_uint(As[mr + 8][kk + t + 4]);
                }
#pragma unroll
                for (int ni = 0; ni < 4; ni++) {
                    int nr = curV + wn * 32 + ni * 8 + g;
                    bf[ni][0] = __float_as_uint(Vs[nr][kk + t]);
                    bf[ni][1] = __float_as_uint(Vs[nr][kk + t + 4]);
                }
#pragma unroll
                for (int mi = 0; mi < 2; mi++)
#pragma unroll
                    for (int ni = 0; ni < 4; ni++)
                        mma_tf32(acc[mi][ni], af[mi], bf[ni]);
            }
            __syncthreads();

            if (it + 2 < NT) {
                cpV_chunk36(Vb + (it + 2) * 32, S_,
                            sV + (uint32_t)(it & 1) * BUFV, tid);
                CP_COMMIT();
            }
            if (it + 1 < NT) {
                if (it + 2 < NT) { CP_WAIT1(); } else { CP_WAIT0(); }
                __syncthreads();
            }
        }

        // epilogue: O = rinv_row * acc
        float* Cb = g_C + ((size_t)b * S_ + q0) * D_ + h * HD_;
#pragma unroll
        for (int mi = 0; mi < 2; mi++) {
            int row = wm * 32 + mi * 16 + g;
            float rv0 = Rs[row], rv1 = Rs[row + 8];
#pragma unroll
            for (int ni = 0; ni < 4; ni++) {
                int col = wn * 32 + ni * 8 + 2 * t;
                float2 o0, o1;
                o0.x = f2tf(acc[mi][ni][0] * rv0); o0.y = f2tf(acc[mi][ni][1] * rv0);
                o1.x = f2tf(acc[mi][ni][2] * rv1); o1.y = f2tf(acc[mi][ni][3] * rv1);
                *(float2*)(Cb + (size_t)row * D_ + col)       = o0;
                *(float2*)(Cb + (size_t)(row + 8) * D_ + col) = o1;
            }
        }
    }
}

// ---------------------------------------------------------------------------
extern "C" void kernel_launch(void* const* d_in, const int* in_sizes, int n_in,
                              void* d_out, int out_size)
{
    const float* q  = (const float*)d_in[0];
    const float* k  = (const float*)d_in[1];
    const float* v  = (const float*)d_in[2];
    const float* Wq = (const float*)d_in[3];
    const float* bq = (const float*)d_in[4];
    const float* Wk = (const float*)d_in[5];
    const float* bk = (const float*)d_in[6];
    const float* Wv = (const float*)d_in[7];
    const float* bv = (const float*)d_in[8];
    const float* Wo = (const float*)d_in[9];
    const float* bo = (const float*)d_in[10];

    float* out  = (float*)d_out;
    float* attn = out + (size_t)MS_ * D_;   // tuple order: (output, attention)

    float *pQ, *pK, *pV, *pVT, *pC, *pWT;
    cudaGetSymbolAddress((void**)&pQ, g_Q);
    cudaGetSymbolAddress((void**)&pK, g_K);
    cudaGetSymbolAddress((void**)&pV, g_V);
    cudaGetSymbolAddress((void**)&pVT, g_VT);
    cudaGetSymbolAddress((void**)&pC, g_C);
    cudaGetSymbolAddress((void**)&pWT, g_WT);

    cudaFuncSetAttribute(qkv_gemm,
                         cudaFuncAttributeMaxDynamicSharedMemorySize, GEMM_SMEM);
    cudaFuncSetAttribute(out_gemm,
                         cudaFuncAttributeMaxDynamicSharedMemorySize, GEMM_SMEM);
    cudaFuncSetAttribute(attn_fused,
                         cudaFuncAttributeMaxDynamicSharedMemorySize, FUSED_SMEM);

    float* WTq = pWT + 0 * (size_t)D_ * D_;
    float* WTk = pWT + 1 * (size_t)D_ * D_;
    float* WTv = pWT + 2 * (size_t)D_ * D_;
    float* WTo = pWT + 3 * (size_t)D_ * D_;

    transpose4<<<dim3(32, 32, 4), dim3(32, 8)>>>(Wq, Wk, Wv, Wo,
                                                 WTq, WTk, WTv, WTo);

    qkv_gemm<<<dim3(8, 64, 3), 256, GEMM_SMEM>>>(q, k, v, WTq, WTk, WTv,
                                                 bq, bk, bv, pQ, pK, pV);

    vtrans<<<dim3(64, 2, 64), dim3(32, 8)>>>(pV, pVT);

    attn_fused<<<dim3(16, 64), 256, FUSED_SMEM>>>(attn);

    out_gemm<<<dim3(8, 64), 256, GEMM_SMEM>>>(pC, WTo, bo, out);
}

// round 17
// speedup vs baseline: 1.4128x; 1.1859x over previous
#include <cuda_runtime.h>
#include <cuda_fp16.h>
#include <math.h>
#include <stdint.h>

#define B_  4
#define S_  2048
#define D_  1024
#define H_  16
#define HD_ 64
#define MS_ (B_*S_)   // 8192

// Scratch (static device globals — no allocation)
__device__ __half g_Qh[(size_t)MS_ * D_];   // Q/8, fp16
__device__ __half g_Kh[(size_t)MS_ * D_];
__device__ __half g_Vh[(size_t)MS_ * D_];
__device__ __half g_VTh[(size_t)B_ * H_ * HD_ * S_];  // V^T per head [bh][hd][s]
__device__ float  g_C[(size_t)MS_ * D_];
__device__ float  g_WT[4][(size_t)D_ * D_];  // transposed + tf32-rounded weights

#define GEMM_SMEM  (512 * 36 * 4)     // 73728 B
// fused: Qs 128x72 h (4608 f) | Ks 2x128x72 h (9216 f) | Ls 512 f | Rs 128 f
#define FUSED_SMEM (14464 * 4)        // 57856 B

// ---------------------------------------------------------------------------
// MMA / cp.async helpers (sm_80+ ISA — compiles for plain sm_103 target)
// ---------------------------------------------------------------------------
__device__ __forceinline__ float f2tf(float f) {
    uint32_t u;
    asm("cvt.rna.tf32.f32 %0, %1;" : "=r"(u) : "f"(f));
    return __uint_as_float(u);
}

__device__ __forceinline__ void mma_tf32(float* d, const uint32_t* a, const uint32_t* b) {
    asm volatile(
        "mma.sync.aligned.m16n8k8.row.col.f32.tf32.tf32.f32 "
        "{%0,%1,%2,%3}, {%4,%5,%6,%7}, {%8,%9}, {%0,%1,%2,%3};"
        : "+f"(d[0]), "+f"(d[1]), "+f"(d[2]), "+f"(d[3])
        : "r"(a[0]), "r"(a[1]), "r"(a[2]), "r"(a[3]),
          "r"(b[0]), "r"(b[1]));
}

__device__ __forceinline__ void mma_f16(float* d, const uint32_t* a, const uint32_t* b) {
    asm volatile(
        "mma.sync.aligned.m16n8k16.row.col.f32.f16.f16.f32 "
        "{%0,%1,%2,%3}, {%4,%5,%6,%7}, {%8,%9}, {%0,%1,%2,%3};"
        : "+f"(d[0]), "+f"(d[1]), "+f"(d[2]), "+f"(d[3])
        : "r"(a[0]), "r"(a[1]), "r"(a[2]), "r"(a[3]),
          "r"(b[0]), "r"(b[1]));
}

__device__ __forceinline__ uint32_t s32(const void* p) {
    return (uint32_t)__cvta_generic_to_shared(p);
}
__device__ __forceinline__ void cp_async16(uint32_t saddr, const void* gaddr) {
    asm volatile("cp.async.cg.shared.global [%0], [%1], 16;"
                 :: "r"(saddr), "l"(gaddr));
}
#define CP_COMMIT() asm volatile("cp.async.commit_group;")
#define CP_WAIT1()  asm volatile("cp.async.wait_group 1;")
#define CP_WAIT0()  asm volatile("cp.async.wait_group 0;")

// fp32: 128 rows x 32 cols chunk -> smem stride 36 (256 threads)
__device__ __forceinline__ void cpB_chunk36(const float* G, int ld,
                                            uint32_t sbase, int tid) {
#pragma unroll
    for (int p = 0; p < 4; p++) {
        int f4 = p * 256 + tid;
        int r = f4 >> 3, c4 = (f4 & 7) * 4;
        cp_async16(sbase + (uint32_t)(r * 36 + c4) * 4, G + (size_t)r * ld + c4);
    }
}
// fp16 K: 128 rows x 64 halves -> smem stride 72 halves (256 threads)
__device__ __forceinline__ void cpKh(const __half* G, int ld,
                                     uint32_t sbase, int tid) {
#pragma unroll
    for (int p = 0; p < 4; p++) {
        int idx = p * 256 + tid;
        int r = idx >> 3, c8 = (idx & 7) * 8;
        cp_async16(sbase + (uint32_t)(r * 72 + c8) * 2, G + (size_t)r * ld + c8);
    }
}
// fp16 V: 64 rows x 32 halves -> smem stride 40 halves (256 threads, 1 cp each)
__device__ __forceinline__ void cpVh(const __half* G, int ld,
                                     uint32_t sbase, int tid) {
    int r = tid >> 2, c8 = (tid & 3) * 8;
    cp_async16(sbase + (uint32_t)(r * 40 + c8) * 2, G + (size_t)r * ld + c8);
}

// ===========================================================================
// Weight transposes (all 4 in one launch) + tf32 pre-round
// ===========================================================================
__global__ __launch_bounds__(256) void transpose4(
    const float* __restrict__ W0, const float* __restrict__ W1,
    const float* __restrict__ W2, const float* __restrict__ W3,
    float* __restrict__ O0, float* __restrict__ O1,
    float* __restrict__ O2, float* __restrict__ O3)
{
    int z = blockIdx.z;
    const float* in = (z == 0) ? W0 : (z == 1) ? W1 : (z == 2) ? W2 : W3;
    float* out      = (z == 0) ? O0 : (z == 1) ? O1 : (z == 2) ? O2 : O3;

    __shared__ float t[32][33];
    int x = blockIdx.x * 32 + threadIdx.x;
    int y = blockIdx.y * 32 + threadIdx.y;
#pragma unroll
    for (int j = 0; j < 32; j += 8)
        t[threadIdx.y + j][threadIdx.x] = in[(size_t)(y + j) * D_ + x];
    __syncthreads();
    x = blockIdx.y * 32 + threadIdx.x;
    y = blockIdx.x * 32 + threadIdx.y;
#pragma unroll
    for (int j = 0; j < 32; j += 8)
        out[(size_t)(y + j) * D_ + x] = f2tf(t[threadIdx.x][threadIdx.y + j]);
}

// ===========================================================================
// V per-head transpose (fp16): g_VTh[bh][hd][s] = g_Vh[(b*S+s)][h*64+hd]
// ===========================================================================
__global__ __launch_bounds__(256) void vtrans(
    const __half* __restrict__ V, __half* __restrict__ VT)
{
    __shared__ float t[32][33];
    int bh = blockIdx.z;
    int b = bh >> 4, h = bh & 15;
    int s0 = blockIdx.x * 32, d0 = blockIdx.y * 32;
#pragma unroll
    for (int j = 0; j < 32; j += 8)
        t[threadIdx.y + j][threadIdx.x] = __half2float(
            V[((size_t)b * S_ + s0 + threadIdx.y + j) * D_ + h * HD_ + d0 + threadIdx.x]);
    __syncthreads();
#pragma unroll
    for (int j = 0; j < 32; j += 8)
        VT[((size_t)bh * HD_ + d0 + threadIdx.y + j) * S_ + s0 + threadIdx.x] =
            __float2half_rn(t[threadIdx.x][threadIdx.y + j]);
}

// ===========================================================================
// 128x128xK tf32 MMA mainloop (projections): A reg prefetch + STS (cvt),
// B via cp.async 2-stage. As/Bs: 256 rows x 36.
// ===========================================================================
template<bool CVTA>
__device__ __forceinline__ void gemm_main(
    const float* __restrict__ A, const float* __restrict__ BT,
    int K, int lda, int ldb,
    float (*As)[36], float (*Bs)[36],
    float (&acc)[4][4][4])
{
    int tid  = threadIdx.x;
    int lane = tid & 31, warp = tid >> 5;
    int g = lane >> 2, t = lane & 3;
    int wm = warp >> 2, wn = warp & 3;

    uint32_t sB = s32(Bs);
    const uint32_t BUFB = 128 * 36 * 4;
    int NT = K / 32;

    float4 pa[4];
#pragma unroll
    for (int p = 0; p < 4; p++) {
        int f4 = p * 256 + tid;
        int r = f4 >> 3, c4 = (f4 & 7) * 4;
        pa[p] = *(const float4*)(A + (size_t)r * lda + c4);
    }
    cpB_chunk36(BT, ldb, sB, tid); CP_COMMIT();
    if (NT > 1) { cpB_chunk36(BT + 32, ldb, sB + BUFB, tid); CP_COMMIT(); }

#pragma unroll
    for (int p = 0; p < 4; p++) {
        int f4 = p * 256 + tid;
        int r = f4 >> 3, c4 = (f4 & 7) * 4;
        As[r][c4 + 0] = CVTA ? f2tf(pa[p].x) : pa[p].x;
        As[r][c4 + 1] = CVTA ? f2tf(pa[p].y) : pa[p].y;
        As[r][c4 + 2] = CVTA ? f2tf(pa[p].z) : pa[p].z;
        As[r][c4 + 3] = CVTA ? f2tf(pa[p].w) : pa[p].w;
    }
    if (NT > 1) {
#pragma unroll
        for (int p = 0; p < 4; p++) {
            int f4 = p * 256 + tid;
            int r = f4 >> 3, c4 = (f4 & 7) * 4;
            pa[p] = *(const float4*)(A + (size_t)r * lda + 32 + c4);
        }
    }
    if (NT > 1) { CP_WAIT1(); } else { CP_WAIT0(); }
    __syncthreads();

    for (int it = 0; it < NT; it++) {
        int cur = (it & 1) * 128;
        if (it + 1 < NT) {
            int nb = ((it + 1) & 1) * 128;
#pragma unroll
            for (int p = 0; p < 4; p++) {
                int f4 = p * 256 + tid;
                int r = nb + (f4 >> 3), c4 = (f4 & 7) * 4;
                As[r][c4 + 0] = CVTA ? f2tf(pa[p].x) : pa[p].x;
                As[r][c4 + 1] = CVTA ? f2tf(pa[p].y) : pa[p].y;
                As[r][c4 + 2] = CVTA ? f2tf(pa[p].z) : pa[p].z;
                As[r][c4 + 3] = CVTA ? f2tf(pa[p].w) : pa[p].w;
            }
        }
        if (it + 2 < NT) {
            int k0 = (it + 2) * 32;
#pragma unroll
            for (int p = 0; p < 4; p++) {
                int f4 = p * 256 + tid;
                int r = f4 >> 3, c4 = (f4 & 7) * 4;
                pa[p] = *(const float4*)(A + (size_t)r * lda + k0 + c4);
            }
        }

#pragma unroll
        for (int kk = 0; kk < 32; kk += 8) {
            uint32_t af[4][4], bf[4][2];
#pragma unroll
            for (int mi = 0; mi < 4; mi++) {
                int mr = cur + wm * 64 + mi * 16 + g;
                af[mi][0] = __float_as_uint(As[mr][kk + t]);
                af[mi][1] = __float_as_uint(As[mr + 8][kk + t]);
                af[mi][2] = __float_as_uint(As[mr][kk + t + 4]);
                af[mi][3] = __float_as_uint(As[mr + 8][kk + t + 4]);
            }
#pragma unroll
            for (int ni = 0; ni < 4; ni++) {
                int nr = cur + wn * 32 + ni * 8 + g;
                bf[ni][0] = __float_as_uint(Bs[nr][kk + t]);
                bf[ni][1] = __float_as_uint(Bs[nr][kk + t + 4]);
            }
#pragma unroll
            for (int mi = 0; mi < 4; mi++)
#pragma unroll
                for (int ni = 0; ni < 4; ni++)
                    mma_tf32(acc[mi][ni], af[mi], bf[ni]);
        }
        __syncthreads();

        if (it + 2 < NT) {
            cpB_chunk36(BT + (it + 2) * 32, ldb,
                        sB + (uint32_t)(it & 1) * BUFB, tid);
            CP_COMMIT();
        }
        if (it + 1 < NT) {
            if (it + 2 < NT) { CP_WAIT1(); } else { CP_WAIT0(); }
            __syncthreads();
        }
    }
}

// ===========================================================================
// Fused Q/K/V projection GEMMs -> fp16 outputs (Q pre-scaled by 1/8).
// ===========================================================================
__global__ __launch_bounds__(256, 2) void qkv_gemm(
    const float* __restrict__ Aq, const float* __restrict__ Ak,
    const float* __restrict__ Av,
    const float* __restrict__ Wq, const float* __restrict__ Wk,
    const float* __restrict__ Wv,
    const float* __restrict__ bq, const float* __restrict__ bk,
    const float* __restrict__ bv,
    __half* __restrict__ Cq, __half* __restrict__ Ck, __half* __restrict__ Cv)
{
    extern __shared__ float sdyn[];
    float (*As)[36] = (float(*)[36])sdyn;
    float (*Bs)[36] = (float(*)[36])sdyn + 256;

    int z = blockIdx.z;
    const float* A    = (z == 0) ? Aq : (z == 1) ? Ak : Av;
    const float* BT   = (z == 0) ? Wq : (z == 1) ? Wk : Wv;
    const float* bias = (z == 0) ? bq : (z == 1) ? bk : bv;
    __half*      C    = (z == 0) ? Cq : (z == 1) ? Ck : Cv;
    const float  sc   = (z == 0) ? 0.125f : 1.0f;

    int m0 = blockIdx.y * 128, n0 = blockIdx.x * 128;

    float acc[4][4][4];
#pragma unroll
    for (int i = 0; i < 4; i++)
#pragma unroll
        for (int j = 0; j < 4; j++)
#pragma unroll
            for (int r = 0; r < 4; r++) acc[i][j][r] = 0.f;

    gemm_main<true>(A + (size_t)m0 * D_, BT + (size_t)n0 * D_,
                    D_, D_, D_, As, Bs, acc);

    int lane = threadIdx.x & 31, warp = threadIdx.x >> 5;
    int g = lane >> 2, t = lane & 3;
    int wm = warp >> 2, wn = warp & 3;
#pragma unroll
    for (int mi = 0; mi < 4; mi++) {
        int row = m0 + wm * 64 + mi * 16 + g;
#pragma unroll
        for (int ni = 0; ni < 4; ni++) {
            int col = n0 + wn * 32 + ni * 8 + 2 * t;
            float2 b2 = *(const float2*)(bias + col);
            *(__half2*)(C + (size_t)row * D_ + col) =
                __floats2half2_rn((acc[mi][ni][0] + b2.x) * sc,
                                  (acc[mi][ni][1] + b2.y) * sc);
            *(__half2*)(C + (size_t)(row + 8) * D_ + col) =
                __floats2half2_rn((acc[mi][ni][2] + b2.x) * sc,
                                  (acc[mi][ni][3] + b2.y) * sc);
        }
    }
}

// ===========================================================================
// Output projection GEMM (tf32, unchanged).
// ===========================================================================
__global__ __launch_bounds__(256, 2) void out_gemm(
    const float* __restrict__ A, const float* __restrict__ BT,
    const float* __restrict__ bias, float* __restrict__ C)
{
    extern __shared__ float sdyn[];
    float (*As)[36] = (float(*)[36])sdyn;
    float (*Bs)[36] = (float(*)[36])sdyn + 256;

    int m0 = blockIdx.y * 128, n0 = blockIdx.x * 128;

    float acc[4][4][4];
#pragma unroll
    for (int i = 0; i < 4; i++)
#pragma unroll
        for (int j = 0; j < 4; j++)
#pragma unroll
            for (int r = 0; r < 4; r++) acc[i][j][r] = 0.f;

    gemm_main<false>(A + (size_t)m0 * D_, BT + (size_t)n0 * D_,
                     D_, D_, D_, As, Bs, acc);

    int lane = threadIdx.x & 31, warp = threadIdx.x >> 5;
    int g = lane >> 2, t = lane & 3;
    int wm = warp >> 2, wn = warp & 3;
#pragma unroll
    for (int mi = 0; mi < 4; mi++) {
        int row = m0 + wm * 64 + mi * 16 + g;
#pragma unroll
        for (int ni = 0; ni < 4; ni++) {
            int col = n0 + wn * 32 + ni * 8 + 2 * t;
            float2 b2 = *(const float2*)(bias + col);
            float2 o0, o1;
            o0.x = acc[mi][ni][0] + b2.x; o0.y = acc[mi][ni][1] + b2.y;
            o1.x = acc[mi][ni][2] + b2.x; o1.y = acc[mi][ni][3] + b2.y;
            *(float2*)(C + (size_t)row * D_ + col)       = o0;
            *(float2*)(C + (size_t)(row + 8) * D_ + col) = o1;
        }
    }
}

// ===========================================================================
// FUSED attention, full fp16 MMA: CTA = 128 q x 2048 k, one (b,h).
// Phase 1: E = exp(Qh.Kh) via m16n8k16 fp16 -> fp16 E in upper row half;
//          row sums -> smem rinv.
// Phase 2: raw fp16 E -> smem (no cvt), P = E*rinv fp32 overwrite,
//          O = rinv*(E@V) fp16 MMA. grid (16,64), 256 thr, 2 CTAs/SM.
// ===========================================================================
__global__ __launch_bounds__(256, 2) void attn_fused(float* __restrict__ attn)
{
    extern __shared__ float sdyn[];
    // phase 1: Qs [128][72]h @0, Ks 2x[128][72]h @4608f, Ls @13824f, Rs @14336f
    __half* Qs = (__half*)sdyn;
    __half* Ks = (__half*)(sdyn + 4608);
    float (*Ls)[4] = (float(*)[4])(sdyn + 13824);
    float* Rs = sdyn + 14336;
    // phase 2: As2 2x[128][40]h @0 (5120f), Vs2 2x[64][40]h @5120f (2560f)
    __half* As2 = (__half*)sdyn;
    __half* Vs2 = (__half*)(sdyn + 5120);

    int tid  = threadIdx.x;
    int lane = tid & 31, warp = tid >> 5;
    int g = lane >> 2, t = lane & 3;

    int bh = blockIdx.y;
    int b = bh >> 4, h = bh & 15;
    int q0 = blockIdx.x * 128;

    const __half* Qb = g_Qh + ((size_t)b * S_ + q0) * D_ + h * HD_;
    const __half* Kb = g_Kh + (size_t)b * S_ * D_ + h * HD_;
    float* Ab = attn + (size_t)bh * S_ * S_ + (size_t)q0 * S_;

    // ==================== Phase 1: E (fp16) + row sums ====================
    {
        int wm = warp >> 2, wn = warp & 3;   // 2(m) x 4(n), warp tile 64x32
        uint32_t sK = s32(Ks);
        const uint32_t BUFK = 128 * 72 * 2;  // 18432 B

        cpKh(Kb, D_, sK, tid); CP_COMMIT();
        cpKh(Kb + (size_t)128 * D_, D_, sK + BUFK, tid); CP_COMMIT();

        // load Q tile 128 x 64 halves
#pragma unroll
        for (int p = 0; p < 4; p++) {
            int idx = p * 256 + tid;
            int r = idx >> 3, c8 = (idx & 7) * 8;
            *(uint4*)(Qs + r * 72 + c8) = *(const uint4*)(Qb + (size_t)r * D_ + c8);
        }

        float l8[8];
#pragma unroll
        for (int i = 0; i < 8; i++) l8[i] = 0.f;

        CP_WAIT1();
        __syncthreads();

        for (int kt = 0; kt < 16; kt++) {
            const __half* Kc = Ks + (kt & 1) * (128 * 72);

            float acc[4][4][4];
#pragma unroll
            for (int i = 0; i < 4; i++)
#pragma unroll
                for (int j = 0; j < 4; j++)
#pragma unroll
                    for (int r = 0; r < 4; r++) acc[i][j][r] = 0.f;

#pragma unroll
            for (int kk = 0; kk < 64; kk += 16) {
                uint32_t af[4][4], bf[4][2];
#pragma unroll
                for (int mi = 0; mi < 4; mi++) {
                    int mr = wm * 64 + mi * 16 + g;
                    const __half* qp = Qs + mr * 72 + kk + 2 * t;
                    af[mi][0] = *(const uint32_t*)(qp);
                    af[mi][1] = *(const uint32_t*)(qp + 576);   // +8 rows
                    af[mi][2] = *(const uint32_t*)(qp + 8);
                    af[mi][3] = *(const uint32_t*)(qp + 584);
                }
#pragma unroll
                for (int ni = 0; ni < 4; ni++) {
                    int nr = wn * 32 + ni * 8 + g;
                    const __half* kp = Kc + nr * 72 + kk + 2 * t;
                    bf[ni][0] = *(const uint32_t*)(kp);
                    bf[ni][1] = *(const uint32_t*)(kp + 8);
                }
#pragma unroll
                for (int mi = 0; mi < 4; mi++)
#pragma unroll
                    for (int ni = 0; ni < 4; ni++)
                        mma_f16(acc[mi][ni], af[mi], bf[ni]);
            }

            // E = exp(score) (scale folded into Q); fp16 store; row sums
#pragma unroll
            for (int mi = 0; mi < 4; mi++) {
                int row = wm * 64 + mi * 16 + g;
                __half2* hrow0 = (__half2*)(Ab + (size_t)row * S_ + 1024);
                __half2* hrow1 = (__half2*)(Ab + (size_t)(row + 8) * S_ + 1024);
#pragma unroll
                for (int ni = 0; ni < 4; ni++) {
                    int col = kt * 128 + wn * 32 + ni * 8 + 2 * t;
#pragma unroll
                    for (int r = 0; r < 4; r++)
                        acc[mi][ni][r] = __expf(acc[mi][ni][r]);
                    hrow0[col >> 1] = __floats2half2_rn(acc[mi][ni][0], acc[mi][ni][1]);
                    hrow1[col >> 1] = __floats2half2_rn(acc[mi][ni][2], acc[mi][ni][3]);
                    l8[mi * 2 + 0] += acc[mi][ni][0] + acc[mi][ni][1];
                    l8[mi * 2 + 1] += acc[mi][ni][2] + acc[mi][ni][3];
                }
            }
            __syncthreads();

            if (kt + 2 < 16) {
                cpKh(Kb + (size_t)(kt + 2) * 128 * D_, D_,
                     sK + (uint32_t)(kt & 1) * BUFK, tid);
                CP_COMMIT();
            }
            if (kt + 1 < 16) {
                if (kt + 2 < 16) { CP_WAIT1(); } else { CP_WAIT0(); }
                __syncthreads();
            }
        }

        // reduce sums over quad lanes t (same rows)
#pragma unroll
        for (int ti = 0; ti < 8; ti++) {
            float l = l8[ti];
            l += __shfl_xor_sync(0xffffffffu, l, 1);
            l += __shfl_xor_sync(0xffffffffu, l, 2);
            l8[ti] = l;
        }
        __syncthreads();
        if (t == 0) {
#pragma unroll
            for (int ti = 0; ti < 8; ti++) {
                int mi = ti >> 1, half = ti & 1;
                int row = wm * 64 + mi * 16 + g + half * 8;
                Ls[row][wn] = l8[ti];
            }
        }
        __syncthreads();
        if (tid < 128) {
            float l = Ls[tid][0] + Ls[tid][1] + Ls[tid][2] + Ls[tid][3];
            Rs[tid] = 1.0f / l;
        }
        __syncthreads();
    }

    // ==================== Phase 2: normalize + E @ V (fp16) ====================
    {
        int wm = warp >> 1, wn = warp & 1;   // 4(m) x 2(n), warp tile 32x32
        const __half* Vb = g_VTh + (size_t)bh * HD_ * S_;   // [hd][s]
        uint32_t sV = s32(Vs2);
        const uint32_t BUFV = 64 * 40 * 2;   // 5120 B
        const int NT = S_ / 32;              // 64

        float acc[2][4][4];
#pragma unroll
        for (int i = 0; i < 2; i++)
#pragma unroll
            for (int j = 0; j < 4; j++)
#pragma unroll
                for (int r = 0; r < 4; r++) acc[i][j][r] = 0.f;

        uint2 pa[4];
#pragma unroll
        for (int p = 0; p < 4; p++) {
            int f4 = p * 256 + tid;
            int r = f4 >> 3, c4 = (f4 & 7) * 4;
            const __half* hp = (const __half*)(Ab + (size_t)r * S_ + 1024);
            pa[p] = *(const uint2*)(hp + c4);
        }
        cpVh(Vb, S_, sV, tid); CP_COMMIT();
        cpVh(Vb + 32, S_, sV + BUFV, tid); CP_COMMIT();

        // transform + STS chunk 0 (P = E*rinv fp32 out; raw fp16 E to smem)
#pragma unroll
        for (int p = 0; p < 4; p++) {
            int f4 = p * 256 + tid;
            int r = f4 >> 3, c4 = (f4 & 7) * 4;
            float rv = Rs[r];
            float2 f0 = __half22float2(*(__half2*)&pa[p].x);
            float2 f1 = __half22float2(*(__half2*)&pa[p].y);
            float4 pr = make_float4(f0.x * rv, f0.y * rv, f1.x * rv, f1.y * rv);
            *(float4*)(Ab + (size_t)r * S_ + c4) = pr;
            *(uint2*)(As2 + r * 40 + c4) = pa[p];
        }
#pragma unroll
        for (int p = 0; p < 4; p++) {
            int f4 = p * 256 + tid;
            int r = f4 >> 3, c4 = (f4 & 7) * 4;
            const __half* hp = (const __half*)(Ab + (size_t)r * S_ + 1024);
            pa[p] = *(const uint2*)(hp + 32 + c4);
        }
        CP_WAIT1();
        __syncthreads();

        for (int it = 0; it < NT; it++) {
            int curA = (it & 1) * 128;
            int curV = (it & 1) * 64;
            if (it + 1 < NT) {
                int nb = ((it + 1) & 1) * 128;
                int kb = (it + 1) * 32;
#pragma unroll
                for (int p = 0; p < 4; p++) {
                    int f4 = p * 256 + tid;
                    int r = f4 >> 3, c4 = (f4 & 7) * 4;
                    float rv = Rs[r];
                    float2 f0 = __half22float2(*(__half2*)&pa[p].x);
                    float2 f1 = __half22float2(*(__half2*)&pa[p].y);
                    float4 pr = make_float4(f0.x * rv, f0.y * rv, f1.x * rv, f1.y * rv);
                    *(float4*)(Ab + (size_t)r * S_ + kb + c4) = pr;
                    *(uint2*)(As2 + (nb + r) * 40 + c4) = pa[p];
                }
            }
            if (it + 2 < NT) {
                int k0 = (it + 2) * 32;
#pragma unroll
                for (int p = 0; p < 4; p++) {
                    int f4 = p * 256 + tid;
                    int r = f4 >> 3, c4 = (f4 & 7) * 4;
                    const __half* hp = (const __half*)(Ab + (size_t)r * S_ + 1024);
                    pa[p] = *(const uint2*)(hp + k0 + c4);
                }
            }

#pragma unroll
            for (int kk = 0; kk < 32; kk += 16) {
                uint32_t af[2][4], bf[4][2];
#pragma unroll
                for (int mi = 0; mi < 2; mi++) {
                    int mr = curA + wm * 32 + mi * 16 + g;
                    const __half* ap = As2 + mr * 40 + kk + 2 * t;
                    af[mi][0] = *(const uint32_t*)(ap);
                    af[mi][1] = *(const uint32_t*)(ap + 320);   // +8 rows
                    af[mi][2] = *(const uint32_t*)(ap + 8);
                    af[mi][3] = *(const uint32_t*)(ap + 328);
                }
#pragma unroll
                for (int ni = 0; ni < 4; ni++) {
                    int nr = curV + wn * 32 + ni * 8 + g;
                    const __half* vp = Vs2 + nr * 40 + kk + 2 * t;
                    bf[ni][0] = *(const uint32_t*)(vp);
                    bf[ni][1] = *(const uint32_t*)(vp + 8);
                }
#pragma unroll
                for (int mi = 0; mi < 2; mi++)
#pragma unroll
                    for (int ni = 0; ni < 4; ni++)
                        mma_f16(acc[mi][ni], af[mi], bf[ni]);
            }
            __syncthreads();

            if (it + 2 < NT) {
                cpVh(Vb + (it + 2) * 32, S_, sV + (uint32_t)(it & 1) * BUFV, tid);
                CP_COMMIT();
            }
            if (it + 1 < NT) {
                if (it + 2 < NT) { CP_WAIT1(); } else { CP_WAIT0(); }
                __syncthreads();
            }
        }

        // epilogue: O = rinv_row * acc -> tf32-rounded fp32 (for out_gemm)
        float* Cb = g_C + ((size_t)b * S_ + q0) * D_ + h * HD_;
#pragma unroll
        for (int mi = 0; mi < 2; mi++) {
            int row = wm * 32 + mi * 16 + g;
            float rv0 = Rs[row], rv1 = Rs[row + 8];
#pragma unroll
            for (int ni = 0; ni < 4; ni++) {
                int col = wn * 32 + ni * 8 + 2 * t;
                float2 o0, o1;
                o0.x = f2tf(acc[mi][ni][0] * rv0); o0.y = f2tf(acc[mi][ni][1] * rv0);
                o1.x = f2tf(acc[mi][ni][2] * rv1); o1.y = f2tf(acc[mi][ni][3] * rv1);
                *(float2*)(Cb + (size_t)row * D_ + col)       = o0;
                *(float2*)(Cb + (size_t)(row + 8) * D_ + col) = o1;
            }
        }
    }
}

// ---------------------------------------------------------------------------
extern "C" void kernel_launch(void* const* d_in, const int* in_sizes, int n_in,
                              void* d_out, int out_size)
{
    const float* q  = (const float*)d_in[0];
    const float* k  = (const float*)d_in[1];
    const float* v  = (const float*)d_in[2];
    const float* Wq = (const float*)d_in[3];
    const float* bq = (const float*)d_in[4];
    const float* Wk = (const float*)d_in[5];
    const float* bk = (const float*)d_in[6];
    const float* Wv = (const float*)d_in[7];
    const float* bv = (const float*)d_in[8];
    const float* Wo = (const float*)d_in[9];
    const float* bo = (const float*)d_in[10];

    float* out  = (float*)d_out;
    float* attn = out + (size_t)MS_ * D_;   // tuple order: (output, attention)

    __half *pQh, *pKh, *pVh, *pVTh;
    float *pC, *pWT;
    cudaGetSymbolAddress((void**)&pQh, g_Qh);
    cudaGetSymbolAddress((void**)&pKh, g_Kh);
    cudaGetSymbolAddress((void**)&pVh, g_Vh);
    cudaGetSymbolAddress((void**)&pVTh, g_VTh);
    cudaGetSymbolAddress((void**)&pC, g_C);
    cudaGetSymbolAddress((void**)&pWT, g_WT);

    cudaFuncSetAttribute(qkv_gemm,
                         cudaFuncAttributeMaxDynamicSharedMemorySize, GEMM_SMEM);
    cudaFuncSetAttribute(out_gemm,
                         cudaFuncAttributeMaxDynamicSharedMemorySize, GEMM_SMEM);
    cudaFuncSetAttribute(attn_fused,
                         cudaFuncAttributeMaxDynamicSharedMemorySize, FUSED_SMEM);

    float* WTq = pWT + 0 * (size_t)D_ * D_;
    float* WTk = pWT + 1 * (size_t)D_ * D_;
    float* WTv = pWT + 2 * (size_t)D_ * D_;
    float* WTo = pWT + 3 * (size_t)D_ * D_;

    transpose4<<<dim3(32, 32, 4), dim3(32, 8)>>>(Wq, Wk, Wv, Wo,
                                                 WTq, WTk, WTv, WTo);

    qkv_gemm<<<dim3(8, 64, 3), 256, GEMM_SMEM>>>(q, k, v, WTq, WTk, WTv,
                                                 bq, bk, bv, pQh, pKh, pVh);

    vtrans<<<dim3(64, 2, 64), dim3(32, 8)>>>(pVh, pVTh);

    attn_fused<<<dim3(16, 64), 256, FUSED_SMEM>>>(attn);

    out_gemm<<<dim3(8, 64), 256, GEMM_SMEM>>>(pC, WTo, bo, out);
}